// round 14
// baseline (speedup 1.0000x reference)
#include <cuda_runtime.h>
#include <cuda_bf16.h>
#include <cstdint>

#define H_  16
#define D_  64
#define DM_ 1024
#define L_  256
#define B_  64
#define M_  (L_*B_)       // 16384
#define N1_ (H_*4*D_)     // 4096
#define HD_ (H_*D_)       // 1024
#define SCALE_ 0.125f
#define LN_EPS_ 1e-5f

// ---------------- scratch ----------------
__device__ __nv_bfloat16 g_hb[M_*DM_];
__device__ __nv_bfloat16 g_wqkv[N1_*DM_];
__device__ __nv_bfloat16 g_wo[DM_*HD_];
__device__ __nv_bfloat16 g_qb [B_*H_*L_*D_];  // post-phi bf16 [B,H,L,D]
__device__ __nv_bfloat16 g_k1b[B_*H_*L_*D_];
__device__ __nv_bfloat16 g_k2b[B_*H_*L_*D_];
__device__ __nv_bfloat16 g_vb [B_*H_*L_*D_];
__device__ __nv_bfloat16 g_lo[M_*HD_];        // gated layer_out
__device__ __nv_bfloat16 g_attnb[M_*DM_];     // attn_out bf16

// ---------------- merged cast kernel ----------------
#define H4_ (M_*DM_/4)
#define Q4_ (N1_*DM_/4)
#define O4_ (DM_*HD_/4)

__global__ void __launch_bounds__(256) cast_all(const float* __restrict__ h,
                                                const float* __restrict__ wq,
                                                const float* __restrict__ wo)
{
    int i = blockIdx.x * blockDim.x + threadIdx.x;
    const float* src;
    __nv_bfloat16* dst;
    int j;
    if (i < H4_)            { src = h;  dst = g_hb;   j = i; }
    else if (i < H4_ + Q4_) { src = wq; dst = g_wqkv; j = i - H4_; }
    else if (i < H4_ + Q4_ + O4_) { src = wo; dst = g_wo; j = i - H4_ - Q4_; }
    else return;
    float4 f = ((const float4*)src)[j];
    __nv_bfloat162* o = ((__nv_bfloat162*)dst) + j * 2;
    o[0] = __floats2bfloat162_rn(f.x, f.y);
    o[1] = __floats2bfloat162_rn(f.z, f.w);
}

// ---------------- mma/ldsm helpers ----------------
__device__ __forceinline__ void mma_bf16(float& d0, float& d1, float& d2, float& d3,
                                         uint32_t a0, uint32_t a1, uint32_t a2, uint32_t a3,
                                         uint32_t b0, uint32_t b1) {
    asm volatile(
        "mma.sync.aligned.m16n8k16.row.col.f32.bf16.bf16.f32 "
        "{%0,%1,%2,%3},{%4,%5,%6,%7},{%8,%9},{%0,%1,%2,%3};\n"
        : "+f"(d0), "+f"(d1), "+f"(d2), "+f"(d3)
        : "r"(a0), "r"(a1), "r"(a2), "r"(a3), "r"(b0), "r"(b1));
}
__device__ __forceinline__ void ldsm4(uint32_t a, uint32_t& r0, uint32_t& r1, uint32_t& r2, uint32_t& r3) {
    asm volatile("ldmatrix.sync.aligned.m8n8.x4.shared.b16 {%0,%1,%2,%3},[%4];"
                 : "=r"(r0), "=r"(r1), "=r"(r2), "=r"(r3) : "r"(a));
}
__device__ __forceinline__ void ldsm4t(uint32_t a, uint32_t& r0, uint32_t& r1, uint32_t& r2, uint32_t& r3) {
    asm volatile("ldmatrix.sync.aligned.m8n8.x4.trans.shared.b16 {%0,%1,%2,%3},[%4];"
                 : "=r"(r0), "=r"(r1), "=r"(r2), "=r"(r3) : "r"(a));
}
__device__ __forceinline__ uint32_t packbf(float a, float b) {
    __nv_bfloat162 t = __floats2bfloat162_rn(a, b);
    return *(uint32_t*)&t;
}
#define CP_ASYNC16(dst, src) asm volatile("cp.async.cg.shared.global [%0], [%1], 16;" :: "r"(dst), "l"(src))
#define CP_COMMIT() asm volatile("cp.async.commit_group;")
#define CP_WAIT(n)  asm volatile("cp.async.wait_group %0;" :: "n"(n))

// ---------------- quad transpose (R13 winner) ----------------
__device__ __forceinline__ void quad_transpose(const uint32_t pk[8], uint32_t wout[8], int lane) {
    const int ql = lane & 3;
    const bool hi2 = (ql & 2) != 0;
    const bool hi1 = (ql & 1) != 0;
    uint32_t kA0 = hi2 ? pk[4] : pk[0];
    uint32_t kA1 = hi2 ? pk[5] : pk[1];
    uint32_t kA2 = hi2 ? pk[6] : pk[2];
    uint32_t kA3 = hi2 ? pk[7] : pk[3];
    uint32_t sA0 = hi2 ? pk[0] : pk[4];
    uint32_t sA1 = hi2 ? pk[1] : pk[5];
    uint32_t sA2 = hi2 ? pk[2] : pk[6];
    uint32_t sA3 = hi2 ? pk[3] : pk[7];
    uint32_t rA0 = __shfl_xor_sync(0xFFFFFFFFu, sA0, 2);
    uint32_t rA1 = __shfl_xor_sync(0xFFFFFFFFu, sA1, 2);
    uint32_t rA2 = __shfl_xor_sync(0xFFFFFFFFu, sA2, 2);
    uint32_t rA3 = __shfl_xor_sync(0xFFFFFFFFu, sA3, 2);
    uint32_t k0 = hi1 ? kA2 : kA0;
    uint32_t k1 = hi1 ? kA3 : kA1;
    uint32_t r0 = hi1 ? rA2 : rA0;
    uint32_t r1 = hi1 ? rA3 : rA1;
    uint32_t sB0 = hi1 ? kA0 : kA2;
    uint32_t sB1 = hi1 ? kA1 : kA3;
    uint32_t sB2 = hi1 ? rA0 : rA2;
    uint32_t sB3 = hi1 ? rA1 : rA3;
    uint32_t b0 = __shfl_xor_sync(0xFFFFFFFFu, sB0, 1);
    uint32_t b1 = __shfl_xor_sync(0xFFFFFFFFu, sB1, 1);
    uint32_t b2 = __shfl_xor_sync(0xFFFFFFFFu, sB2, 1);
    uint32_t b3 = __shfl_xor_sync(0xFFFFFFFFu, sB3, 1);
    #pragma unroll
    for (int h = 0; h < 2; h++) {
        uint32_t a = h ? k1 : k0;
        uint32_t bb = h ? b1 : b0;
        uint32_t cc = h ? r1 : r0;
        uint32_t dd = h ? b3 : b2;
        if (hi1) { uint32_t t = a; a = bb; bb = t; t = cc; cc = dd; dd = t; }
        if (hi2) { uint32_t t = a; a = cc; cc = t; t = bb; bb = dd; dd = t; }
        wout[h * 4 + 0] = a; wout[h * 4 + 1] = bb;
        wout[h * 4 + 2] = cc; wout[h * 4 + 3] = dd;
    }
}

// ---------------- bf16 NT GEMM, 128x128xK128 blocks, 3x64KB stages, 1 CTA/SM ----------------
// 256B rows stored as two swizzled 128B sub-blocks. Halves the per-GEMM sync count.
#define GEMM_SMEM (3 * 65536)   // 192KB

template<int EPI>
__global__ void __launch_bounds__(256) gemm_nt(
    const __nv_bfloat16* __restrict__ A, const __nv_bfloat16* __restrict__ Bw,
    int M, int N, int K, __nv_bfloat16* __restrict__ outp)
{
    extern __shared__ __nv_bfloat16 gsm[];
    const uint32_t smb = (uint32_t)__cvta_generic_to_shared(gsm);

    const int tid = threadIdx.x, lane = tid & 31, w = tid >> 5;
    const int wm = w & 3, wn = w >> 2;
    const int m0 = blockIdx.y * 128, n0 = blockIdx.x * 128;

    // loader: rows lr+32g (g<4), chunk pair {lcc, lcc+8} of 16 chunks per 256B row
    const int lr = tid >> 3, lcc = tid & 7;
    const __nv_bfloat16* Ag = A + (size_t)(m0 + lr) * K + lcc * 8;
    const __nv_bfloat16* Bg = Bw + (size_t)(n0 + lr) * K + lcc * 8;
    uint32_t stoff[4];
    #pragma unroll
    for (int g = 0; g < 4; g++) {
        int r = lr + 32 * g;
        stoff[g] = r * 256 + ((lcc ^ (r & 7)) * 16);   // sub-block 0; +128 for sub-block 1
    }

    const int aRow = wm * 32 + ((lane >> 3) & 1) * 8 + (lane & 7);
    const int aCk  = (lane >> 4);
    const int bRow = wn * 64 + (lane >> 4) * 8 + (lane & 7);
    const int bCk  = ((lane >> 3) & 1);

    float acc[2][8][4];
    #pragma unroll
    for (int i = 0; i < 2; i++)
        #pragma unroll
        for (int j = 0; j < 8; j++)
            #pragma unroll
            for (int k = 0; k < 4; k++) acc[i][j][k] = 0.f;

    const int nk = K >> 7;   // 8 for K=1024
    const int kbase = ((blockIdx.x + blockIdx.y) & 1) * (nk >> 1);

    auto issue_stage = [&](int st, int kb) {
        uint32_t ab = smb + st * 65536u, bb = ab + 32768u;
        #pragma unroll
        for (int g = 0; g < 4; g++) {
            const __nv_bfloat16* ap = Ag + (size_t)(32 * g) * K + kb * 128;
            const __nv_bfloat16* bp = Bg + (size_t)(32 * g) * K + kb * 128;
            CP_ASYNC16(ab + stoff[g],        ap);
            CP_ASYNC16(ab + stoff[g] + 128u, ap + 64);
            CP_ASYNC16(bb + stoff[g],        bp);
            CP_ASYNC16(bb + stoff[g] + 128u, bp + 64);
        }
        CP_COMMIT();
    };

    issue_stage(0, kbase & (nk - 1));
    issue_stage(1, (1 + kbase) & (nk - 1));

    for (int i = 0; i < nk; i++) {
        CP_WAIT(1);
        __syncthreads();
        if (i + 2 < nk)
            issue_stage((i + 2) % 3, (i + 2 + kbase) & (nk - 1));

        const uint32_t ab = smb + (i % 3) * 65536u;
        const uint32_t bb = ab + 32768u;
        #pragma unroll
        for (int kk = 0; kk < 16; kk += 2) {
            uint32_t af[2][4], bfr[4][4];
            #pragma unroll
            for (int mt = 0; mt < 2; mt++) {
                int r = aRow + mt * 16, ck = kk + aCk;
                ldsm4(ab + r * 256 + ((ck >> 3) << 7) + (((ck & 7) ^ (r & 7)) * 16),
                      af[mt][0], af[mt][1], af[mt][2], af[mt][3]);
            }
            #pragma unroll
            for (int np = 0; np < 4; np++) {
                int r = bRow + np * 16, ck = kk + bCk;
                ldsm4(bb + r * 256 + ((ck >> 3) << 7) + (((ck & 7) ^ (r & 7)) * 16),
                      bfr[np][0], bfr[np][1], bfr[np][2], bfr[np][3]);
            }
            #pragma unroll
            for (int mt = 0; mt < 2; mt++)
                #pragma unroll
                for (int np = 0; np < 4; np++) {
                    mma_bf16(acc[mt][2*np][0], acc[mt][2*np][1], acc[mt][2*np][2], acc[mt][2*np][3],
                             af[mt][0], af[mt][1], af[mt][2], af[mt][3], bfr[np][0], bfr[np][1]);
                    mma_bf16(acc[mt][2*np+1][0], acc[mt][2*np+1][1], acc[mt][2*np+1][2], acc[mt][2*np+1][3],
                             af[mt][0], af[mt][1], af[mt][2], af[mt][3], bfr[np][2], bfr[np][3]);
                }
        }
    }

    // ---------------- epilogue (quad-transposed 16B stores) ----------------
    const int ql = lane & 3;
    #pragma unroll
    for (int mt = 0; mt < 2; mt++) {
        #pragma unroll
        for (int rr = 0; rr < 2; rr++) {
            int m = m0 + wm * 32 + mt * 16 + (lane >> 2) + rr * 8;
            uint32_t pk[8], wd[8];
            #pragma unroll
            for (int nt = 0; nt < 8; nt++)
                pk[nt] = packbf(acc[mt][nt][rr * 2], acc[mt][nt][rr * 2 + 1]);
            quad_transpose(pk, wd, lane);

            if (EPI == 0) {
                const int c0base = n0 + wn * 64;
                const int head = c0base >> 8, part = (c0base >> 6) & 3;
                __nv_bfloat16* dst = (part == 0) ? g_qb : (part == 1) ? g_k1b
                                   : (part == 2) ? g_k2b : g_vb;
                if (part < 3) {
                    float v[16];
                    #pragma unroll
                    for (int j = 0; j < 8; j++) {
                        __nv_bfloat162 p = *(__nv_bfloat162*)&wd[j];
                        float a = __bfloat162float(p.x), bq = __bfloat162float(p.y);
                        v[2*j]   = (a  > 0.f) ? (a  + 1.f) : __expf(a);
                        v[2*j+1] = (bq > 0.f) ? (bq + 1.f) : __expf(bq);
                    }
                    float s = 0.f;
                    #pragma unroll
                    for (int j = 0; j < 16; j++) s += v[j];
                    s += __shfl_xor_sync(0xFFFFFFFFu, s, 1);
                    s += __shfl_xor_sync(0xFFFFFFFFu, s, 2);
                    float inv = 1.f / s;
                    #pragma unroll
                    for (int j = 0; j < 8; j++)
                        wd[j] = packbf(v[2*j] * inv, v[2*j+1] * inv);
                }
                int l = m >> 6, b = m & 63;
                __nv_bfloat16* rowp = dst + (((size_t)(b * H_ + head) * L_ + l) << 6) + 16 * ql;
                *(uint4*)rowp       = make_uint4(wd[0], wd[1], wd[2], wd[3]);
                *(uint4*)(rowp + 8) = make_uint4(wd[4], wd[5], wd[6], wd[7]);
            } else {
                __nv_bfloat16* rowp = outp + (size_t)m * N + n0 + wn * 64 + 16 * ql;
                *(uint4*)rowp       = make_uint4(wd[0], wd[1], wd[2], wd[3]);
                *(uint4*)(rowp + 8) = make_uint4(wd[4], wd[5], wd[6], wd[7]);
            }
        }
    }
}

// ---------------- fast-weight: register-resident S + merged O/W phase, last-chunk W skip ----------------
#define FW_SMEM (12 * 4096 * 2)   // 96KB

__device__ __forceinline__ int offe(int t, int r, int c) {
    return t * 4096 + r * 64 + ((((c >> 3) ^ (r & 7))) << 3) + (c & 7);
}

__global__ void __launch_bounds__(256) fw_kernel(const float* __restrict__ pi0,
                                                 __nv_bfloat16* __restrict__ lo)
{
    extern __shared__ __nv_bfloat16 fs[];
    const uint32_t sb = (uint32_t)__cvta_generic_to_shared(fs);
    const int bh = blockIdx.x, b = bh >> 4, h = bh & 15;
    const int tid = threadIdx.x, lane = tid & 31, warp = tid >> 5;
    const int g = warp >> 2, wg = warp & 3;
    const size_t base = (size_t)bh * (L_ * D_);
    const __nv_bfloat16* srcs[4] = { g_qb + base, g_k1b + base, g_k2b + base, g_vb + base };

    const int lr = tid >> 3, lcc = tid & 7;

    const int arow = 16 * wg + ((lane >> 3) & 1) * 8 + (lane & 7);
    const int ac0  = (lane >> 4);
    const int brow = (lane >> 4) * 8 + (lane & 7);
    const int bck  = ((lane >> 3) & 1);
    const int trow = ((lane >> 3) & 1) * 8 + (lane & 7);
    const int tck  = (lane >> 4);
    const int karow = (lane >> 4) * 8 + (lane & 7);
    const int kack  = ((lane >> 3) & 1);
    const int tlo = 16 * wg + (lane >> 2);
    const int cc0 = (lane & 3) * 2;

    float Wa[8][4], O[8][4];
    #pragma unroll
    for (int n = 0; n < 8; n++)
        #pragma unroll
        for (int q = 0; q < 4; q++) Wa[n][q] = 0.f;

    #pragma unroll
    for (int t = 0; t < 4; t++) {
        const __nv_bfloat16* sp = srcs[t];
        #pragma unroll
        for (int g2 = 0; g2 < 2; g2++) {
            int r = lr + 32 * g2;
            CP_ASYNC16(sb + 2u * offe(t, r, lcc * 8), sp + r * 64 + lcc * 8);
        }
    }
    CP_COMMIT();

    for (int c = 0; c < 4; c++) {
        __syncthreads();
        if (c + 1 < 4) {
            int s4 = ((c + 1) & 1) * 4;
            #pragma unroll
            for (int t = 0; t < 4; t++) {
                const __nv_bfloat16* sp = srcs[t] + (c + 1) * 4096;
                #pragma unroll
                for (int g2 = 0; g2 < 2; g2++) {
                    int r = lr + 32 * g2;
                    CP_ASYNC16(sb + 2u * offe(s4 + t, r, lcc * 8), sp + r * 64 + lcc * 8);
                }
            }
        }
        CP_COMMIT();
        CP_WAIT(1);

        if (c) {
            #pragma unroll
            for (int n = 0; n < 8; n++) {
                #pragma unroll
                for (int hf = 0; hf < 2; hf++) {
                    int r = 16 * wg + (lane >> 2) + 8 * hf;
                    *(__nv_bfloat162*)&fs[offe(10 + g, r, 8 * n + cc0)] =
                        __floats2bfloat162_rn(Wa[n][2*hf], Wa[n][2*hf+1]);
                }
            }
        }
        __syncthreads();

        const int tb = (c & 1) * 4;

        uint32_t QA[4][4];
        #pragma unroll
        for (int ks = 0; ks < 4; ks++)
            ldsm4(sb + 2u * offe(tb + 0, arow, (2 * ks + ac0) * 8), QA[ks][0], QA[ks][1], QA[ks][2], QA[ks][3]);

        #pragma unroll
        for (int n = 0; n < 8; n++)
            #pragma unroll
            for (int q = 0; q < 4; q++) O[n][q] = 0.f;
        #pragma unroll
        for (int ks = 0; ks < 4; ks++)
            #pragma unroll
            for (int np = 0; np < 4; np++) {
                uint32_t b0, b1, b2, b3;
                ldsm4(sb + 2u * offe(tb + 1 + g, 16 * np + brow, (2 * ks + bck) * 8), b0, b1, b2, b3);
                mma_bf16(O[2*np][0], O[2*np][1], O[2*np][2], O[2*np][3],
                         QA[ks][0], QA[ks][1], QA[ks][2], QA[ks][3], b0, b1);
                mma_bf16(O[2*np+1][0], O[2*np+1][1], O[2*np+1][2], O[2*np+1][3],
                         QA[ks][0], QA[ks][1], QA[ks][2], QA[ks][3], b2, b3);
            }

        uint32_t SA[4][4];
        #pragma unroll
        for (int kb = 0; kb < 4; kb++) {
            #pragma unroll
            for (int half = 0; half < 2; half++) {
                int nt = 2 * kb + half;
                int s0 = 8 * nt + cc0;
                float v0 = (s0     <= tlo) ? O[nt][0] : 0.f;
                float v1 = (s0 + 1 <= tlo) ? O[nt][1] : 0.f;
                float v2 = (s0     <= tlo + 8) ? O[nt][2] : 0.f;
                float v3 = (s0 + 1 <= tlo + 8) ? O[nt][3] : 0.f;
                SA[kb][2*half]     = packbf(v0, v1);
                SA[kb][2*half + 1] = packbf(v2, v3);
            }
        }
        #pragma unroll
        for (int n = 0; n < 8; n++)
            #pragma unroll
            for (int q = 0; q < 4; q++) O[n][q] = 0.f;

        #pragma unroll
        for (int ks = 0; ks < 4; ks++) {
            uint32_t KA[4];
            if (c < 3)
                ldsm4t(sb + 2u * offe(tb + 1 + g, 16 * ks + karow, (2 * wg + kack) * 8),
                       KA[0], KA[1], KA[2], KA[3]);
            #pragma unroll
            for (int np = 0; np < 4; np++) {
                uint32_t vb0, vb1, vb2, vb3;
                ldsm4t(sb + 2u * offe(tb + 3, 16 * ks + trow, (2 * np + tck) * 8), vb0, vb1, vb2, vb3);
                mma_bf16(O[2*np][0], O[2*np][1], O[2*np][2], O[2*np][3],
                         SA[ks][0], SA[ks][1], SA[ks][2], SA[ks][3], vb0, vb1);
                mma_bf16(O[2*np+1][0], O[2*np+1][1], O[2*np+1][2], O[2*np+1][3],
                         SA[ks][0], SA[ks][1], SA[ks][2], SA[ks][3], vb2, vb3);
                if (c < 3) {
                    mma_bf16(Wa[2*np][0], Wa[2*np][1], Wa[2*np][2], Wa[2*np][3],
                             KA[0], KA[1], KA[2], KA[3], vb0, vb1);
                    mma_bf16(Wa[2*np+1][0], Wa[2*np+1][1], Wa[2*np+1][2], Wa[2*np+1][3],
                             KA[0], KA[1], KA[2], KA[3], vb2, vb3);
                }
                if (c) {
                    uint32_t wb0, wb1, wb2, wb3;
                    ldsm4t(sb + 2u * offe(10 + g, 16 * ks + trow, (2 * np + tck) * 8), wb0, wb1, wb2, wb3);
                    mma_bf16(O[2*np][0], O[2*np][1], O[2*np][2], O[2*np][3],
                             QA[ks][0], QA[ks][1], QA[ks][2], QA[ks][3], wb0, wb1);
                    mma_bf16(O[2*np+1][0], O[2*np+1][1], O[2*np+1][2], O[2*np+1][3],
                             QA[ks][0], QA[ks][1], QA[ks][2], QA[ks][3], wb2, wb3);
                }
            }
        }

        {
            int l0 = c * 64 + tlo, l1 = l0 + 8;
            float p0 = fminf(fmaxf(pi0[h * 256 + l0], 0.f), 1.f);
            float p1 = fminf(fmaxf(pi0[h * 256 + l1], 0.f), 1.f);
            if (g == 1) {
                float q0 = SCALE_ * (1.f - p0), q1 = SCALE_ * (1.f - p1);
                #pragma unroll
                for (int nt = 0; nt < 8; nt++) {
                    int s0 = 8 * nt + cc0;
                    *(__nv_bfloat162*)&fs[offe(9, tlo, s0)]     = __floats2bfloat162_rn(q0 * O[nt][0], q0 * O[nt][1]);
                    *(__nv_bfloat162*)&fs[offe(9, tlo + 8, s0)] = __floats2bfloat162_rn(q1 * O[nt][2], q1 * O[nt][3]);
                }
            }
            __syncthreads();
            if (g == 0) {
                float q0 = SCALE_ * p0, q1 = SCALE_ * p1;
                size_t ro0 = ((size_t)(l0 * B_ + b)) * HD_ + h * 64;
                size_t ro1 = ((size_t)(l1 * B_ + b)) * HD_ + h * 64;
                #pragma unroll
                for (int nt = 0; nt < 8; nt++) {
                    int e0 = 8 * nt + cc0;
                    __nv_bfloat162 x0 = *(__nv_bfloat162*)&fs[offe(9, tlo, e0)];
                    __nv_bfloat162 x1 = *(__nv_bfloat162*)&fs[offe(9, tlo + 8, e0)];
                    float f0 = q0 * O[nt][0] + __bfloat162float(x0.x);
                    float f1 = q0 * O[nt][1] + __bfloat162float(x0.y);
                    float f2 = q1 * O[nt][2] + __bfloat162float(x1.x);
                    float f3 = q1 * O[nt][3] + __bfloat162float(x1.y);
                    *(__nv_bfloat162*)&lo[ro0 + e0] = __floats2bfloat162_rn(f0, f1);
                    *(__nv_bfloat162*)&lo[ro1 + e0] = __floats2bfloat162_rn(f2, f3);
                }
            }
        }
    }
}

// ---------------- residual + LayerNorm: warp-per-row ----------------
__global__ void __launch_bounds__(256) ln_kernel(const float* __restrict__ hin,
                                                 const __nv_bfloat16* __restrict__ attn,
                                                 const float* __restrict__ gamma,
                                                 const float* __restrict__ beta,
                                                 float* __restrict__ out)
{
    const int warp = threadIdx.x >> 5, lane = threadIdx.x & 31;
    const int row = blockIdx.x * 8 + warp;
    const float4* hr = (const float4*)(hin + (size_t)row * DM_);
    const uint2*  ar = (const uint2*)(attn + (size_t)row * DM_);

    float x[32];
    float s = 0.f, sq = 0.f;
    #pragma unroll
    for (int j = 0; j < 8; j++) {
        float4 hv = hr[lane + 32 * j];
        uint2 ap = ar[lane + 32 * j];
        __nv_bfloat162 a0 = *(__nv_bfloat162*)&ap.x;
        __nv_bfloat162 a1 = *(__nv_bfloat162*)&ap.y;
        float v0 = hv.x + __bfloat162float(a0.x);
        float v1 = hv.y + __bfloat162float(a0.y);
        float v2 = hv.z + __bfloat162float(a1.x);
        float v3 = hv.w + __bfloat162float(a1.y);
        x[4*j] = v0; x[4*j+1] = v1; x[4*j+2] = v2; x[4*j+3] = v3;
        s  += v0 + v1 + v2 + v3;
        sq += v0*v0 + v1*v1 + v2*v2 + v3*v3;
    }
    #pragma unroll
    for (int o = 16; o > 0; o >>= 1) {
        s  += __shfl_xor_sync(0xFFFFFFFFu, s,  o);
        sq += __shfl_xor_sync(0xFFFFFFFFu, sq, o);
    }
    float mu  = s * (1.f / DM_);
    float var = sq * (1.f / DM_) - mu * mu;
    float inv = rsqrtf(var + LN_EPS_);

    float4* orow = (float4*)(out + (size_t)row * DM_);
    #pragma unroll
    for (int j = 0; j < 8; j++) {
        float4 g4 = ((const float4*)gamma)[lane + 32 * j];
        float4 b4 = ((const float4*)beta)[lane + 32 * j];
        float4 o4;
        o4.x = (x[4*j]   - mu) * inv * g4.x + b4.x;
        o4.y = (x[4*j+1] - mu) * inv * g4.y + b4.y;
        o4.z = (x[4*j+2] - mu) * inv * g4.z + b4.z;
        o4.w = (x[4*j+3] - mu) * inv * g4.w + b4.w;
        orow[lane + 32 * j] = o4;
    }
}

// ---------------- launch ----------------
extern "C" void kernel_launch(void* const* d_in, const int* in_sizes, int n_in,
                              void* d_out, int out_size) {
    (void)in_sizes; (void)n_in; (void)out_size;
    const float* h      = (const float*)d_in[0];
    const float* qkv_w  = (const float*)d_in[1];
    const float* o_w    = (const float*)d_in[2];
    const float* gamma  = (const float*)d_in[3];
    const float* beta   = (const float*)d_in[4];
    const float* pi0    = (const float*)d_in[5];
    float* out = (float*)d_out;

    __nv_bfloat16 *hb, *wqkv, *wo, *lo, *attnb;
    cudaGetSymbolAddress((void**)&hb,    g_hb);
    cudaGetSymbolAddress((void**)&wqkv,  g_wqkv);
    cudaGetSymbolAddress((void**)&wo,    g_wo);
    cudaGetSymbolAddress((void**)&lo,    g_lo);
    cudaGetSymbolAddress((void**)&attnb, g_attnb);

    cudaFuncSetAttribute(gemm_nt<0>, cudaFuncAttributeMaxDynamicSharedMemorySize, GEMM_SMEM);
    cudaFuncSetAttribute(gemm_nt<1>, cudaFuncAttributeMaxDynamicSharedMemorySize, GEMM_SMEM);
    cudaFuncSetAttribute(fw_kernel,  cudaFuncAttributeMaxDynamicSharedMemorySize, FW_SMEM);

    cast_all<<<(H4_ + Q4_ + O4_ + 255) / 256, 256>>>(h, qkv_w, o_w);

    gemm_nt<0><<<dim3(N1_/128, M_/128), 256, GEMM_SMEM>>>(hb, wqkv, M_, N1_, DM_, nullptr);

    fw_kernel<<<B_*H_, 256, FW_SMEM>>>(pi0, lo);

    gemm_nt<1><<<dim3(HD_/128, M_/128), 256, GEMM_SMEM>>>(lo, wo, M_, HD_, HD_, attnb);

    ln_kernel<<<M_/8, 256>>>(h, attnb, gamma, beta, out);
}

// round 15
// speedup vs baseline: 1.1203x; 1.1203x over previous
#include <cuda_runtime.h>
#include <cuda_bf16.h>
#include <cstdint>

#define H_  16
#define D_  64
#define DM_ 1024
#define L_  256
#define B_  64
#define M_  (L_*B_)       // 16384
#define N1_ (H_*4*D_)     // 4096
#define HD_ (H_*D_)       // 1024
#define SCALE_ 0.125f
#define LN_EPS_ 1e-5f

// ---------------- scratch ----------------
__device__ __nv_bfloat16 g_hb[M_*DM_];
__device__ __nv_bfloat16 g_wqkv[N1_*DM_];
__device__ __nv_bfloat16 g_wo[DM_*HD_];
__device__ __nv_bfloat16 g_qb [B_*H_*L_*D_];  // post-phi bf16 [B,H,L,D]
__device__ __nv_bfloat16 g_k1b[B_*H_*L_*D_];
__device__ __nv_bfloat16 g_k2b[B_*H_*L_*D_];
__device__ __nv_bfloat16 g_vb [B_*H_*L_*D_];
__device__ __nv_bfloat16 g_lo[M_*HD_];        // gated layer_out
__device__ __nv_bfloat16 g_attnb[M_*DM_];     // attn_out bf16

// ---------------- merged cast kernel ----------------
#define H4_ (M_*DM_/4)
#define Q4_ (N1_*DM_/4)
#define O4_ (DM_*HD_/4)

__global__ void __launch_bounds__(256) cast_all(const float* __restrict__ h,
                                                const float* __restrict__ wq,
                                                const float* __restrict__ wo)
{
    int i = blockIdx.x * blockDim.x + threadIdx.x;
    const float* src;
    __nv_bfloat16* dst;
    int j;
    if (i < H4_)            { src = h;  dst = g_hb;   j = i; }
    else if (i < H4_ + Q4_) { src = wq; dst = g_wqkv; j = i - H4_; }
    else if (i < H4_ + Q4_ + O4_) { src = wo; dst = g_wo; j = i - H4_ - Q4_; }
    else return;
    float4 f = ((const float4*)src)[j];
    __nv_bfloat162* o = ((__nv_bfloat162*)dst) + j * 2;
    o[0] = __floats2bfloat162_rn(f.x, f.y);
    o[1] = __floats2bfloat162_rn(f.z, f.w);
}

// ---------------- mma/ldsm helpers ----------------
__device__ __forceinline__ void mma_bf16(float& d0, float& d1, float& d2, float& d3,
                                         uint32_t a0, uint32_t a1, uint32_t a2, uint32_t a3,
                                         uint32_t b0, uint32_t b1) {
    asm volatile(
        "mma.sync.aligned.m16n8k16.row.col.f32.bf16.bf16.f32 "
        "{%0,%1,%2,%3},{%4,%5,%6,%7},{%8,%9},{%0,%1,%2,%3};\n"
        : "+f"(d0), "+f"(d1), "+f"(d2), "+f"(d3)
        : "r"(a0), "r"(a1), "r"(a2), "r"(a3), "r"(b0), "r"(b1));
}
__device__ __forceinline__ void ldsm4(uint32_t a, uint32_t& r0, uint32_t& r1, uint32_t& r2, uint32_t& r3) {
    asm volatile("ldmatrix.sync.aligned.m8n8.x4.shared.b16 {%0,%1,%2,%3},[%4];"
                 : "=r"(r0), "=r"(r1), "=r"(r2), "=r"(r3) : "r"(a));
}
__device__ __forceinline__ void ldsm4t(uint32_t a, uint32_t& r0, uint32_t& r1, uint32_t& r2, uint32_t& r3) {
    asm volatile("ldmatrix.sync.aligned.m8n8.x4.trans.shared.b16 {%0,%1,%2,%3},[%4];"
                 : "=r"(r0), "=r"(r1), "=r"(r2), "=r"(r3) : "r"(a));
}
__device__ __forceinline__ uint32_t packbf(float a, float b) {
    __nv_bfloat162 t = __floats2bfloat162_rn(a, b);
    return *(uint32_t*)&t;
}
#define CP_ASYNC16(dst, src) asm volatile("cp.async.cg.shared.global [%0], [%1], 16;" :: "r"(dst), "l"(src))
#define CP_COMMIT() asm volatile("cp.async.commit_group;")
#define CP_WAIT(n)  asm volatile("cp.async.wait_group %0;" :: "n"(n))

// ---------------- quad transpose (R13 winner) ----------------
// In: pk[nt] = bf16x2 of cols {nt*8 + ql*2, +1} of this thread's row (quad-uniform row).
// Out: wout[0..7] covering contiguous cols [16*ql, 16*ql+16).
__device__ __forceinline__ void quad_transpose(const uint32_t pk[8], uint32_t wout[8], int lane) {
    const int ql = lane & 3;
    const bool hi2 = (ql & 2) != 0;
    const bool hi1 = (ql & 1) != 0;
    uint32_t kA0 = hi2 ? pk[4] : pk[0];
    uint32_t kA1 = hi2 ? pk[5] : pk[1];
    uint32_t kA2 = hi2 ? pk[6] : pk[2];
    uint32_t kA3 = hi2 ? pk[7] : pk[3];
    uint32_t sA0 = hi2 ? pk[0] : pk[4];
    uint32_t sA1 = hi2 ? pk[1] : pk[5];
    uint32_t sA2 = hi2 ? pk[2] : pk[6];
    uint32_t sA3 = hi2 ? pk[3] : pk[7];
    uint32_t rA0 = __shfl_xor_sync(0xFFFFFFFFu, sA0, 2);
    uint32_t rA1 = __shfl_xor_sync(0xFFFFFFFFu, sA1, 2);
    uint32_t rA2 = __shfl_xor_sync(0xFFFFFFFFu, sA2, 2);
    uint32_t rA3 = __shfl_xor_sync(0xFFFFFFFFu, sA3, 2);
    uint32_t k0 = hi1 ? kA2 : kA0;
    uint32_t k1 = hi1 ? kA3 : kA1;
    uint32_t r0 = hi1 ? rA2 : rA0;
    uint32_t r1 = hi1 ? rA3 : rA1;
    uint32_t sB0 = hi1 ? kA0 : kA2;
    uint32_t sB1 = hi1 ? kA1 : kA3;
    uint32_t sB2 = hi1 ? rA0 : rA2;
    uint32_t sB3 = hi1 ? rA1 : rA3;
    uint32_t b0 = __shfl_xor_sync(0xFFFFFFFFu, sB0, 1);
    uint32_t b1 = __shfl_xor_sync(0xFFFFFFFFu, sB1, 1);
    uint32_t b2 = __shfl_xor_sync(0xFFFFFFFFu, sB2, 1);
    uint32_t b3 = __shfl_xor_sync(0xFFFFFFFFu, sB3, 1);
    #pragma unroll
    for (int h = 0; h < 2; h++) {
        uint32_t a = h ? k1 : k0;
        uint32_t bb = h ? b1 : b0;
        uint32_t cc = h ? r1 : r0;
        uint32_t dd = h ? b3 : b2;
        if (hi1) { uint32_t t = a; a = bb; bb = t; t = cc; cc = dd; dd = t; }
        if (hi2) { uint32_t t = a; a = cc; cc = t; t = bb; bb = dd; dd = t; }
        wout[h * 4 + 0] = a; wout[h * 4 + 1] = bb;
        wout[h * 4 + 2] = cc; wout[h * 4 + 3] = dd;
    }
}

// ---------------- bf16 NT GEMM, 128x128x64, 3-stage cp.async, K-phase desync (R13 winner) ----------------
#define GEMM_SMEM (3 * 32768)   // 96KB

template<int EPI>
__global__ void __launch_bounds__(256, 2) gemm_nt(
    const __nv_bfloat16* __restrict__ A, const __nv_bfloat16* __restrict__ Bw,
    int M, int N, int K, __nv_bfloat16* __restrict__ outp)
{
    extern __shared__ __nv_bfloat16 gsm[];
    const uint32_t smb = (uint32_t)__cvta_generic_to_shared(gsm);

    const int tid = threadIdx.x, lane = tid & 31, w = tid >> 5;
    const int wm = w & 3, wn = w >> 2;
    const int m0 = blockIdx.y * 128, n0 = blockIdx.x * 128;

    const int lr = tid >> 3, lcc = tid & 7;
    const __nv_bfloat16* Ag = A + (size_t)(m0 + lr) * K + lcc * 8;
    const __nv_bfloat16* Bg = Bw + (size_t)(n0 + lr) * K + lcc * 8;
    uint32_t stoff[4];
    #pragma unroll
    for (int g = 0; g < 4; g++) {
        int r = lr + 32 * g;
        stoff[g] = r * 128 + ((lcc ^ (r & 7)) * 16);
    }

    const int aRow = wm * 32 + ((lane >> 3) & 1) * 8 + (lane & 7);
    const int aCk  = (lane >> 4);
    const int bRow = wn * 64 + (lane >> 4) * 8 + (lane & 7);
    const int bCk  = ((lane >> 3) & 1);

    float acc[2][8][4];
    #pragma unroll
    for (int i = 0; i < 2; i++)
        #pragma unroll
        for (int j = 0; j < 8; j++)
            #pragma unroll
            for (int k = 0; k < 4; k++) acc[i][j][k] = 0.f;

    const int nk = K >> 6;
    const int kbase = ((blockIdx.x + blockIdx.y) & 1) * (nk >> 1);

    #pragma unroll
    for (int s = 0; s < 2; s++) {
        int kb = (s + kbase) & (nk - 1);
        uint32_t ab = smb + s * 32768u, bb = ab + 16384u;
        #pragma unroll
        for (int g = 0; g < 4; g++) {
            CP_ASYNC16(ab + stoff[g], Ag + (size_t)(32 * g) * K + kb * 64);
            CP_ASYNC16(bb + stoff[g], Bg + (size_t)(32 * g) * K + kb * 64);
        }
        CP_COMMIT();
    }

    for (int i = 0; i < nk; i++) {
        CP_WAIT(1);
        __syncthreads();
        if (i + 2 < nk) {
            int st = (i + 2) % 3;
            int kbn = (i + 2 + kbase) & (nk - 1);
            uint32_t ab = smb + st * 32768u, bb = ab + 16384u;
            #pragma unroll
            for (int g = 0; g < 4; g++) {
                CP_ASYNC16(ab + stoff[g], Ag + (size_t)(32 * g) * K + kbn * 64);
                CP_ASYNC16(bb + stoff[g], Bg + (size_t)(32 * g) * K + kbn * 64);
            }
        }
        CP_COMMIT();

        const uint32_t ab = smb + (i % 3) * 32768u;
        const uint32_t bb = ab + 16384u;
        #pragma unroll
        for (int kk8 = 0; kk8 < 8; kk8 += 2) {
            uint32_t af[2][4], bfr[4][4];
            #pragma unroll
            for (int mt = 0; mt < 2; mt++) {
                int r = aRow + mt * 16, ck = kk8 + aCk;
                ldsm4(ab + r * 128 + ((ck ^ (r & 7)) * 16), af[mt][0], af[mt][1], af[mt][2], af[mt][3]);
            }
            #pragma unroll
            for (int np = 0; np < 4; np++) {
                int r = bRow + np * 16, ck = kk8 + bCk;
                ldsm4(bb + r * 128 + ((ck ^ (r & 7)) * 16), bfr[np][0], bfr[np][1], bfr[np][2], bfr[np][3]);
            }
            #pragma unroll
            for (int mt = 0; mt < 2; mt++)
                #pragma unroll
                for (int np = 0; np < 4; np++) {
                    mma_bf16(acc[mt][2*np][0], acc[mt][2*np][1], acc[mt][2*np][2], acc[mt][2*np][3],
                             af[mt][0], af[mt][1], af[mt][2], af[mt][3], bfr[np][0], bfr[np][1]);
                    mma_bf16(acc[mt][2*np+1][0], acc[mt][2*np+1][1], acc[mt][2*np+1][2], acc[mt][2*np+1][3],
                             af[mt][0], af[mt][1], af[mt][2], af[mt][3], bfr[np][2], bfr[np][3]);
                }
        }
    }

    // ---------------- epilogue (quad-transposed 16B stores) ----------------
    const int ql = lane & 3;
    #pragma unroll
    for (int mt = 0; mt < 2; mt++) {
        #pragma unroll
        for (int rr = 0; rr < 2; rr++) {
            int m = m0 + wm * 32 + mt * 16 + (lane >> 2) + rr * 8;
            uint32_t pk[8], wd[8];
            #pragma unroll
            for (int nt = 0; nt < 8; nt++)
                pk[nt] = packbf(acc[mt][nt][rr * 2], acc[mt][nt][rr * 2 + 1]);
            quad_transpose(pk, wd, lane);

            if (EPI == 0) {
                const int c0base = n0 + wn * 64;
                const int head = c0base >> 8, part = (c0base >> 6) & 3;
                __nv_bfloat16* dst = (part == 0) ? g_qb : (part == 1) ? g_k1b
                                   : (part == 2) ? g_k2b : g_vb;
                if (part < 3) {
                    float v[16];
                    #pragma unroll
                    for (int j = 0; j < 8; j++) {
                        __nv_bfloat162 p = *(__nv_bfloat162*)&wd[j];
                        float a = __bfloat162float(p.x), bq = __bfloat162float(p.y);
                        v[2*j]   = (a  > 0.f) ? (a  + 1.f) : __expf(a);
                        v[2*j+1] = (bq > 0.f) ? (bq + 1.f) : __expf(bq);
                    }
                    float s = 0.f;
                    #pragma unroll
                    for (int j = 0; j < 16; j++) s += v[j];
                    s += __shfl_xor_sync(0xFFFFFFFFu, s, 1);
                    s += __shfl_xor_sync(0xFFFFFFFFu, s, 2);
                    float inv = 1.f / s;
                    #pragma unroll
                    for (int j = 0; j < 8; j++)
                        wd[j] = packbf(v[2*j] * inv, v[2*j+1] * inv);
                }
                int l = m >> 6, b = m & 63;
                __nv_bfloat16* rowp = dst + (((size_t)(b * H_ + head) * L_ + l) << 6) + 16 * ql;
                *(uint4*)rowp       = make_uint4(wd[0], wd[1], wd[2], wd[3]);
                *(uint4*)(rowp + 8) = make_uint4(wd[4], wd[5], wd[6], wd[7]);
            } else {
                __nv_bfloat16* rowp = outp + (size_t)m * N + n0 + wn * 64 + 16 * ql;
                *(uint4*)rowp       = make_uint4(wd[0], wd[1], wd[2], wd[3]);
                *(uint4*)(rowp + 8) = make_uint4(wd[4], wd[5], wd[6], wd[7]);
            }
        }
    }
}

// ---------------- fast-weight: register-resident S + merged O/W phase, wide lo stores ----------------
#define FW_SMEM (12 * 4096 * 2)   // 96KB

__device__ __forceinline__ int offe(int t, int r, int c) {
    return t * 4096 + r * 64 + ((((c >> 3) ^ (r & 7))) << 3) + (c & 7);
}

__global__ void __launch_bounds__(256) fw_kernel(const float* __restrict__ pi0,
                                                 __nv_bfloat16* __restrict__ lo)
{
    extern __shared__ __nv_bfloat16 fs[];
    const uint32_t sb = (uint32_t)__cvta_generic_to_shared(fs);
    const int bh = blockIdx.x, b = bh >> 4, h = bh & 15;
    const int tid = threadIdx.x, lane = tid & 31, warp = tid >> 5;
    const int g = warp >> 2, wg = warp & 3;
    const size_t base = (size_t)bh * (L_ * D_);
    const __nv_bfloat16* srcs[4] = { g_qb + base, g_k1b + base, g_k2b + base, g_vb + base };

    const int lr = tid >> 3, lcc = tid & 7;

    const int arow = 16 * wg + ((lane >> 3) & 1) * 8 + (lane & 7);
    const int ac0  = (lane >> 4);
    const int brow = (lane >> 4) * 8 + (lane & 7);
    const int bck  = ((lane >> 3) & 1);
    const int trow = ((lane >> 3) & 1) * 8 + (lane & 7);
    const int tck  = (lane >> 4);
    const int karow = (lane >> 4) * 8 + (lane & 7);
    const int kack  = ((lane >> 3) & 1);
    const int tlo = 16 * wg + (lane >> 2);
    const int cc0 = (lane & 3) * 2;
    const int ql  = lane & 3;

    float Wa[8][4], O[8][4];
    #pragma unroll
    for (int n = 0; n < 8; n++)
        #pragma unroll
        for (int q = 0; q < 4; q++) Wa[n][q] = 0.f;

    #pragma unroll
    for (int t = 0; t < 4; t++) {
        const __nv_bfloat16* sp = srcs[t];
        #pragma unroll
        for (int g2 = 0; g2 < 2; g2++) {
            int r = lr + 32 * g2;
            CP_ASYNC16(sb + 2u * offe(t, r, lcc * 8), sp + r * 64 + lcc * 8);
        }
    }
    CP_COMMIT();

    for (int c = 0; c < 4; c++) {
        __syncthreads();
        if (c + 1 < 4) {
            int s4 = ((c + 1) & 1) * 4;
            #pragma unroll
            for (int t = 0; t < 4; t++) {
                const __nv_bfloat16* sp = srcs[t] + (c + 1) * 4096;
                #pragma unroll
                for (int g2 = 0; g2 < 2; g2++) {
                    int r = lr + 32 * g2;
                    CP_ASYNC16(sb + 2u * offe(s4 + t, r, lcc * 8), sp + r * 64 + lcc * 8);
                }
            }
        }
        CP_COMMIT();
        CP_WAIT(1);

        if (c) {
            #pragma unroll
            for (int n = 0; n < 8; n++) {
                #pragma unroll
                for (int hf = 0; hf < 2; hf++) {
                    int r = 16 * wg + (lane >> 2) + 8 * hf;
                    *(__nv_bfloat162*)&fs[offe(10 + g, r, 8 * n + cc0)] =
                        __floats2bfloat162_rn(Wa[n][2*hf], Wa[n][2*hf+1]);
                }
            }
        }
        __syncthreads();

        const int tb = (c & 1) * 4;

        uint32_t QA[4][4];
        #pragma unroll
        for (int ks = 0; ks < 4; ks++)
            ldsm4(sb + 2u * offe(tb + 0, arow, (2 * ks + ac0) * 8), QA[ks][0], QA[ks][1], QA[ks][2], QA[ks][3]);

        #pragma unroll
        for (int n = 0; n < 8; n++)
            #pragma unroll
            for (int q = 0; q < 4; q++) O[n][q] = 0.f;
        #pragma unroll
        for (int ks = 0; ks < 4; ks++)
            #pragma unroll
            for (int np = 0; np < 4; np++) {
                uint32_t b0, b1, b2, b3;
                ldsm4(sb + 2u * offe(tb + 1 + g, 16 * np + brow, (2 * ks + bck) * 8), b0, b1, b2, b3);
                mma_bf16(O[2*np][0], O[2*np][1], O[2*np][2], O[2*np][3],
                         QA[ks][0], QA[ks][1], QA[ks][2], QA[ks][3], b0, b1);
                mma_bf16(O[2*np+1][0], O[2*np+1][1], O[2*np+1][2], O[2*np+1][3],
                         QA[ks][0], QA[ks][1], QA[ks][2], QA[ks][3], b2, b3);
            }

        uint32_t SA[4][4];
        #pragma unroll
        for (int kb = 0; kb < 4; kb++) {
            #pragma unroll
            for (int half = 0; half < 2; half++) {
                int nt = 2 * kb + half;
                int s0 = 8 * nt + cc0;
                float v0 = (s0     <= tlo) ? O[nt][0] : 0.f;
                float v1 = (s0 + 1 <= tlo) ? O[nt][1] : 0.f;
                float v2 = (s0     <= tlo + 8) ? O[nt][2] : 0.f;
                float v3 = (s0 + 1 <= tlo + 8) ? O[nt][3] : 0.f;
                SA[kb][2*half]     = packbf(v0, v1);
                SA[kb][2*half + 1] = packbf(v2, v3);
            }
        }
        #pragma unroll
        for (int n = 0; n < 8; n++)
            #pragma unroll
            for (int q = 0; q < 4; q++) O[n][q] = 0.f;

        #pragma unroll
        for (int ks = 0; ks < 4; ks++) {
            uint32_t KA[4];
            if (c < 3)
                ldsm4t(sb + 2u * offe(tb + 1 + g, 16 * ks + karow, (2 * wg + kack) * 8),
                       KA[0], KA[1], KA[2], KA[3]);
            #pragma unroll
            for (int np = 0; np < 4; np++) {
                uint32_t vb0, vb1, vb2, vb3;
                ldsm4t(sb + 2u * offe(tb + 3, 16 * ks + trow, (2 * np + tck) * 8), vb0, vb1, vb2, vb3);
                mma_bf16(O[2*np][0], O[2*np][1], O[2*np][2], O[2*np][3],
                         SA[ks][0], SA[ks][1], SA[ks][2], SA[ks][3], vb0, vb1);
                mma_bf16(O[2*np+1][0], O[2*np+1][1], O[2*np+1][2], O[2*np+1][3],
                         SA[ks][0], SA[ks][1], SA[ks][2], SA[ks][3], vb2, vb3);
                if (c < 3) {
                    mma_bf16(Wa[2*np][0], Wa[2*np][1], Wa[2*np][2], Wa[2*np][3],
                             KA[0], KA[1], KA[2], KA[3], vb0, vb1);
                    mma_bf16(Wa[2*np+1][0], Wa[2*np+1][1], Wa[2*np+1][2], Wa[2*np+1][3],
                             KA[0], KA[1], KA[2], KA[3], vb2, vb3);
                }
                if (c) {
                    uint32_t wb0, wb1, wb2, wb3;
                    ldsm4t(sb + 2u * offe(10 + g, 16 * ks + trow, (2 * np + tck) * 8), wb0, wb1, wb2, wb3);
                    mma_bf16(O[2*np][0], O[2*np][1], O[2*np][2], O[2*np][3],
                             QA[ks][0], QA[ks][1], QA[ks][2], QA[ks][3], wb0, wb1);
                    mma_bf16(O[2*np+1][0], O[2*np+1][1], O[2*np+1][2], O[2*np+1][3],
                             QA[ks][0], QA[ks][1], QA[ks][2], QA[ks][3], wb2, wb3);
                }
            }
        }

        // ---- gate via tile 9 exchange + quad-transposed wide stores ----
        {
            int l0 = c * 64 + tlo, l1 = l0 + 8;
            float p0 = fminf(fmaxf(pi0[h * 256 + l0], 0.f), 1.f);
            float p1 = fminf(fmaxf(pi0[h * 256 + l1], 0.f), 1.f);
            if (g == 1) {
                float q0 = SCALE_ * (1.f - p0), q1 = SCALE_ * (1.f - p1);
                #pragma unroll
                for (int nt = 0; nt < 8; nt++) {
                    int s0 = 8 * nt + cc0;
                    *(__nv_bfloat162*)&fs[offe(9, tlo, s0)]     = __floats2bfloat162_rn(q0 * O[nt][0], q0 * O[nt][1]);
                    *(__nv_bfloat162*)&fs[offe(9, tlo + 8, s0)] = __floats2bfloat162_rn(q1 * O[nt][2], q1 * O[nt][3]);
                }
            }
            __syncthreads();
            if (g == 0) {
                float q0 = SCALE_ * p0, q1 = SCALE_ * p1;
                uint32_t p0k[8], p1k[8], w0[8], w1[8];
                #pragma unroll
                for (int nt = 0; nt < 8; nt++) {
                    int e0 = 8 * nt + cc0;
                    __nv_bfloat162 x0 = *(__nv_bfloat162*)&fs[offe(9, tlo, e0)];
                    __nv_bfloat162 x1 = *(__nv_bfloat162*)&fs[offe(9, tlo + 8, e0)];
                    float f0 = q0 * O[nt][0] + __bfloat162float(x0.x);
                    float f1 = q0 * O[nt][1] + __bfloat162float(x0.y);
                    float f2 = q1 * O[nt][2] + __bfloat162float(x1.x);
                    float f3 = q1 * O[nt][3] + __bfloat162float(x1.y);
                    p0k[nt] = packbf(f0, f1);
                    p1k[nt] = packbf(f2, f3);
                }
                quad_transpose(p0k, w0, lane);
                quad_transpose(p1k, w1, lane);
                __nv_bfloat16* r0p = lo + ((size_t)(l0 * B_ + b)) * HD_ + h * 64 + 16 * ql;
                __nv_bfloat16* r1p = lo + ((size_t)(l1 * B_ + b)) * HD_ + h * 64 + 16 * ql;
                *(uint4*)r0p       = make_uint4(w0[0], w0[1], w0[2], w0[3]);
                *(uint4*)(r0p + 8) = make_uint4(w0[4], w0[5], w0[6], w0[7]);
                *(uint4*)r1p       = make_uint4(w1[0], w1[1], w1[2], w1[3]);
                *(uint4*)(r1p + 8) = make_uint4(w1[4], w1[5], w1[6], w1[7]);
            }
        }
    }
}

// ---------------- residual + LayerNorm: warp-per-row ----------------
__global__ void __launch_bounds__(256) ln_kernel(const float* __restrict__ hin,
                                                 const __nv_bfloat16* __restrict__ attn,
                                                 const float* __restrict__ gamma,
                                                 const float* __restrict__ beta,
                                                 float* __restrict__ out)
{
    const int warp = threadIdx.x >> 5, lane = threadIdx.x & 31;
    const int row = blockIdx.x * 8 + warp;
    const float4* hr = (const float4*)(hin + (size_t)row * DM_);
    const uint2*  ar = (const uint2*)(attn + (size_t)row * DM_);

    float x[32];
    float s = 0.f, sq = 0.f;
    #pragma unroll
    for (int j = 0; j < 8; j++) {
        float4 hv = hr[lane + 32 * j];
        uint2 ap = ar[lane + 32 * j];
        __nv_bfloat162 a0 = *(__nv_bfloat162*)&ap.x;
        __nv_bfloat162 a1 = *(__nv_bfloat162*)&ap.y;
        float v0 = hv.x + __bfloat162float(a0.x);
        float v1 = hv.y + __bfloat162float(a0.y);
        float v2 = hv.z + __bfloat162float(a1.x);
        float v3 = hv.w + __bfloat162float(a1.y);
        x[4*j] = v0; x[4*j+1] = v1; x[4*j+2] = v2; x[4*j+3] = v3;
        s  += v0 + v1 + v2 + v3;
        sq += v0*v0 + v1*v1 + v2*v2 + v3*v3;
    }
    #pragma unroll
    for (int o = 16; o > 0; o >>= 1) {
        s  += __shfl_xor_sync(0xFFFFFFFFu, s,  o);
        sq += __shfl_xor_sync(0xFFFFFFFFu, sq, o);
    }
    float mu  = s * (1.f / DM_);
    float var = sq * (1.f / DM_) - mu * mu;
    float inv = rsqrtf(var + LN_EPS_);

    float4* orow = (float4*)(out + (size_t)row * DM_);
    #pragma unroll
    for (int j = 0; j < 8; j++) {
        float4 g4 = ((const float4*)gamma)[lane + 32 * j];
        float4 b4 = ((const float4*)beta)[lane + 32 * j];
        float4 o4;
        o4.x = (x[4*j]   - mu) * inv * g4.x + b4.x;
        o4.y = (x[4*j+1] - mu) * inv * g4.y + b4.y;
        o4.z = (x[4*j+2] - mu) * inv * g4.z + b4.z;
        o4.w = (x[4*j+3] - mu) * inv * g4.w + b4.w;
        orow[lane + 32 * j] = o4;
    }
}

// ---------------- launch ----------------
extern "C" void kernel_launch(void* const* d_in, const int* in_sizes, int n_in,
                              void* d_out, int out_size) {
    (void)in_sizes; (void)n_in; (void)out_size;
    const float* h      = (const float*)d_in[0];
    const float* qkv_w  = (const float*)d_in[1];
    const float* o_w    = (const float*)d_in[2];
    const float* gamma  = (const float*)d_in[3];
    const float* beta   = (const float*)d_in[4];
    const float* pi0    = (const float*)d_in[5];
    float* out = (float*)d_out;

    __nv_bfloat16 *hb, *wqkv, *wo, *lo, *attnb;
    cudaGetSymbolAddress((void**)&hb,    g_hb);
    cudaGetSymbolAddress((void**)&wqkv,  g_wqkv);
    cudaGetSymbolAddress((void**)&wo,    g_wo);
    cudaGetSymbolAddress((void**)&lo,    g_lo);
    cudaGetSymbolAddress((void**)&attnb, g_attnb);

    cudaFuncSetAttribute(gemm_nt<0>, cudaFuncAttributeMaxDynamicSharedMemorySize, GEMM_SMEM);
    cudaFuncSetAttribute(gemm_nt<1>, cudaFuncAttributeMaxDynamicSharedMemorySize, GEMM_SMEM);
    cudaFuncSetAttribute(fw_kernel,  cudaFuncAttributeMaxDynamicSharedMemorySize, FW_SMEM);

    cast_all<<<(H4_ + Q4_ + O4_ + 255) / 256, 256>>>(h, qkv_w, o_w);

    gemm_nt<0><<<dim3(N1_/128, M_/128), 256, GEMM_SMEM>>>(hb, wqkv, M_, N1_, DM_, nullptr);

    fw_kernel<<<B_*H_, 256, FW_SMEM>>>(pi0, lo);

    gemm_nt<1><<<dim3(HD_/128, M_/128), 256, GEMM_SMEM>>>(lo, wo, M_, HD_, HD_, attnb);

    ln_kernel<<<M_/8, 256>>>(h, attnb, gamma, beta, out);
}

// round 16
// speedup vs baseline: 1.1330x; 1.0114x over previous
#include <cuda_runtime.h>
#include <cuda_bf16.h>
#include <cstdint>

#define H_  16
#define D_  64
#define DM_ 1024
#define L_  256
#define B_  64
#define M_  (L_*B_)       // 16384
#define N1_ (H_*4*D_)     // 4096
#define HD_ (H_*D_)       // 1024
#define SCALE_ 0.125f
#define LN_EPS_ 1e-5f

// ---------------- scratch ----------------
__device__ __nv_bfloat16 g_hb[M_*DM_];
__device__ __nv_bfloat16 g_wqkv[N1_*DM_];
__device__ __nv_bfloat16 g_wo[DM_*HD_];
__device__ __nv_bfloat16 g_qb [B_*H_*L_*D_];  // post-phi bf16 [B,H,L,D]
__device__ __nv_bfloat16 g_k1b[B_*H_*L_*D_];
__device__ __nv_bfloat16 g_k2b[B_*H_*L_*D_];
__device__ __nv_bfloat16 g_vb [B_*H_*L_*D_];
__device__ __nv_bfloat16 g_lo[M_*HD_];        // gated layer_out
__device__ __nv_bfloat16 g_attnb[M_*DM_];     // attn_out bf16

// ---------------- merged cast kernel ----------------
#define H4_ (M_*DM_/4)
#define Q4_ (N1_*DM_/4)
#define O4_ (DM_*HD_/4)

__global__ void __launch_bounds__(256) cast_all(const float* __restrict__ h,
                                                const float* __restrict__ wq,
                                                const float* __restrict__ wo)
{
    int i = blockIdx.x * blockDim.x + threadIdx.x;
    const float* src;
    __nv_bfloat16* dst;
    int j;
    if (i < H4_)            { src = h;  dst = g_hb;   j = i; }
    else if (i < H4_ + Q4_) { src = wq; dst = g_wqkv; j = i - H4_; }
    else if (i < H4_ + Q4_ + O4_) { src = wo; dst = g_wo; j = i - H4_ - Q4_; }
    else return;
    float4 f = ((const float4*)src)[j];
    __nv_bfloat162* o = ((__nv_bfloat162*)dst) + j * 2;
    o[0] = __floats2bfloat162_rn(f.x, f.y);
    o[1] = __floats2bfloat162_rn(f.z, f.w);
}

// ---------------- mma/ldsm helpers ----------------
__device__ __forceinline__ void mma_bf16(float& d0, float& d1, float& d2, float& d3,
                                         uint32_t a0, uint32_t a1, uint32_t a2, uint32_t a3,
                                         uint32_t b0, uint32_t b1) {
    asm volatile(
        "mma.sync.aligned.m16n8k16.row.col.f32.bf16.bf16.f32 "
        "{%0,%1,%2,%3},{%4,%5,%6,%7},{%8,%9},{%0,%1,%2,%3};\n"
        : "+f"(d0), "+f"(d1), "+f"(d2), "+f"(d3)
        : "r"(a0), "r"(a1), "r"(a2), "r"(a3), "r"(b0), "r"(b1));
}
__device__ __forceinline__ void ldsm4(uint32_t a, uint32_t& r0, uint32_t& r1, uint32_t& r2, uint32_t& r3) {
    asm volatile("ldmatrix.sync.aligned.m8n8.x4.shared.b16 {%0,%1,%2,%3},[%4];"
                 : "=r"(r0), "=r"(r1), "=r"(r2), "=r"(r3) : "r"(a));
}
__device__ __forceinline__ void ldsm4t(uint32_t a, uint32_t& r0, uint32_t& r1, uint32_t& r2, uint32_t& r3) {
    asm volatile("ldmatrix.sync.aligned.m8n8.x4.trans.shared.b16 {%0,%1,%2,%3},[%4];"
                 : "=r"(r0), "=r"(r1), "=r"(r2), "=r"(r3) : "r"(a));
}
__device__ __forceinline__ uint32_t packbf(float a, float b) {
    __nv_bfloat162 t = __floats2bfloat162_rn(a, b);
    return *(uint32_t*)&t;
}
#define CP_ASYNC16(dst, src) asm volatile("cp.async.cg.shared.global [%0], [%1], 16;" :: "r"(dst), "l"(src))
#define CP_COMMIT() asm volatile("cp.async.commit_group;")
#define CP_WAIT(n)  asm volatile("cp.async.wait_group %0;" :: "n"(n))

// ---------------- quad transpose (R13 winner, gemm epilogues only) ----------------
__device__ __forceinline__ void quad_transpose(const uint32_t pk[8], uint32_t wout[8], int lane) {
    const int ql = lane & 3;
    const bool hi2 = (ql & 2) != 0;
    const bool hi1 = (ql & 1) != 0;
    uint32_t kA0 = hi2 ? pk[4] : pk[0];
    uint32_t kA1 = hi2 ? pk[5] : pk[1];
    uint32_t kA2 = hi2 ? pk[6] : pk[2];
    uint32_t kA3 = hi2 ? pk[7] : pk[3];
    uint32_t sA0 = hi2 ? pk[0] : pk[4];
    uint32_t sA1 = hi2 ? pk[1] : pk[5];
    uint32_t sA2 = hi2 ? pk[2] : pk[6];
    uint32_t sA3 = hi2 ? pk[3] : pk[7];
    uint32_t rA0 = __shfl_xor_sync(0xFFFFFFFFu, sA0, 2);
    uint32_t rA1 = __shfl_xor_sync(0xFFFFFFFFu, sA1, 2);
    uint32_t rA2 = __shfl_xor_sync(0xFFFFFFFFu, sA2, 2);
    uint32_t rA3 = __shfl_xor_sync(0xFFFFFFFFu, sA3, 2);
    uint32_t k0 = hi1 ? kA2 : kA0;
    uint32_t k1 = hi1 ? kA3 : kA1;
    uint32_t r0 = hi1 ? rA2 : rA0;
    uint32_t r1 = hi1 ? rA3 : rA1;
    uint32_t sB0 = hi1 ? kA0 : kA2;
    uint32_t sB1 = hi1 ? kA1 : kA3;
    uint32_t sB2 = hi1 ? rA0 : rA2;
    uint32_t sB3 = hi1 ? rA1 : rA3;
    uint32_t b0 = __shfl_xor_sync(0xFFFFFFFFu, sB0, 1);
    uint32_t b1 = __shfl_xor_sync(0xFFFFFFFFu, sB1, 1);
    uint32_t b2 = __shfl_xor_sync(0xFFFFFFFFu, sB2, 1);
    uint32_t b3 = __shfl_xor_sync(0xFFFFFFFFu, sB3, 1);
    #pragma unroll
    for (int h = 0; h < 2; h++) {
        uint32_t a = h ? k1 : k0;
        uint32_t bb = h ? b1 : b0;
        uint32_t cc = h ? r1 : r0;
        uint32_t dd = h ? b3 : b2;
        if (hi1) { uint32_t t = a; a = bb; bb = t; t = cc; cc = dd; dd = t; }
        if (hi2) { uint32_t t = a; a = cc; cc = t; t = bb; bb = dd; dd = t; }
        wout[h * 4 + 0] = a; wout[h * 4 + 1] = bb;
        wout[h * 4 + 2] = cc; wout[h * 4 + 3] = dd;
    }
}

// ---------------- bf16 NT GEMM, 128x128x64, 3-stage cp.async, K-phase desync ----------------
#define GEMM_SMEM (3 * 32768)   // 96KB

template<int EPI>
__global__ void __launch_bounds__(256, 2) gemm_nt(
    const __nv_bfloat16* __restrict__ A, const __nv_bfloat16* __restrict__ Bw,
    int M, int N, int K, __nv_bfloat16* __restrict__ outp)
{
    extern __shared__ __nv_bfloat16 gsm[];
    const uint32_t smb = (uint32_t)__cvta_generic_to_shared(gsm);

    const int tid = threadIdx.x, lane = tid & 31, w = tid >> 5;
    const int wm = w & 3, wn = w >> 2;
    const int m0 = blockIdx.y * 128, n0 = blockIdx.x * 128;

    const int lr = tid >> 3, lcc = tid & 7;
    const __nv_bfloat16* Ag = A + (size_t)(m0 + lr) * K + lcc * 8;
    const __nv_bfloat16* Bg = Bw + (size_t)(n0 + lr) * K + lcc * 8;
    uint32_t stoff[4];
    #pragma unroll
    for (int g = 0; g < 4; g++) {
        int r = lr + 32 * g;
        stoff[g] = r * 128 + ((lcc ^ (r & 7)) * 16);
    }

    const int aRow = wm * 32 + ((lane >> 3) & 1) * 8 + (lane & 7);
    const int aCk  = (lane >> 4);
    const int bRow = wn * 64 + (lane >> 4) * 8 + (lane & 7);
    const int bCk  = ((lane >> 3) & 1);

    float acc[2][8][4];
    #pragma unroll
    for (int i = 0; i < 2; i++)
        #pragma unroll
        for (int j = 0; j < 8; j++)
            #pragma unroll
            for (int k = 0; k < 4; k++) acc[i][j][k] = 0.f;

    const int nk = K >> 6;
    const int kbase = ((blockIdx.x + blockIdx.y) & 1) * (nk >> 1);

    #pragma unroll
    for (int s = 0; s < 2; s++) {
        int kb = (s + kbase) & (nk - 1);
        uint32_t ab = smb + s * 32768u, bb = ab + 16384u;
        #pragma unroll
        for (int g = 0; g < 4; g++) {
            CP_ASYNC16(ab + stoff[g], Ag + (size_t)(32 * g) * K + kb * 64);
            CP_ASYNC16(bb + stoff[g], Bg + (size_t)(32 * g) * K + kb * 64);
        }
        CP_COMMIT();
    }

    for (int i = 0; i < nk; i++) {
        CP_WAIT(1);
        __syncthreads();
        if (i + 2 < nk) {
            int st = (i + 2) % 3;
            int kbn = (i + 2 + kbase) & (nk - 1);
            uint32_t ab = smb + st * 32768u, bb = ab + 16384u;
            #pragma unroll
            for (int g = 0; g < 4; g++) {
                CP_ASYNC16(ab + stoff[g], Ag + (size_t)(32 * g) * K + kbn * 64);
                CP_ASYNC16(bb + stoff[g], Bg + (size_t)(32 * g) * K + kbn * 64);
            }
        }
        CP_COMMIT();

        const uint32_t ab = smb + (i % 3) * 32768u;
        const uint32_t bb = ab + 16384u;
        #pragma unroll
        for (int kk8 = 0; kk8 < 8; kk8 += 2) {
            uint32_t af[2][4], bfr[4][4];
            #pragma unroll
            for (int mt = 0; mt < 2; mt++) {
                int r = aRow + mt * 16, ck = kk8 + aCk;
                ldsm4(ab + r * 128 + ((ck ^ (r & 7)) * 16), af[mt][0], af[mt][1], af[mt][2], af[mt][3]);
            }
            #pragma unroll
            for (int np = 0; np < 4; np++) {
                int r = bRow + np * 16, ck = kk8 + bCk;
                ldsm4(bb + r * 128 + ((ck ^ (r & 7)) * 16), bfr[np][0], bfr[np][1], bfr[np][2], bfr[np][3]);
            }
            #pragma unroll
            for (int mt = 0; mt < 2; mt++)
                #pragma unroll
                for (int np = 0; np < 4; np++) {
                    mma_bf16(acc[mt][2*np][0], acc[mt][2*np][1], acc[mt][2*np][2], acc[mt][2*np][3],
                             af[mt][0], af[mt][1], af[mt][2], af[mt][3], bfr[np][0], bfr[np][1]);
                    mma_bf16(acc[mt][2*np+1][0], acc[mt][2*np+1][1], acc[mt][2*np+1][2], acc[mt][2*np+1][3],
                             af[mt][0], af[mt][1], af[mt][2], af[mt][3], bfr[np][2], bfr[np][3]);
                }
        }
    }

    // ---------------- epilogue (quad-transposed 16B stores) ----------------
    const int ql = lane & 3;
    #pragma unroll
    for (int mt = 0; mt < 2; mt++) {
        #pragma unroll
        for (int rr = 0; rr < 2; rr++) {
            int m = m0 + wm * 32 + mt * 16 + (lane >> 2) + rr * 8;
            uint32_t pk[8], wd[8];
            #pragma unroll
            for (int nt = 0; nt < 8; nt++)
                pk[nt] = packbf(acc[mt][nt][rr * 2], acc[mt][nt][rr * 2 + 1]);
            quad_transpose(pk, wd, lane);

            if (EPI == 0) {
                const int c0base = n0 + wn * 64;
                const int head = c0base >> 8, part = (c0base >> 6) & 3;
                __nv_bfloat16* dst = (part == 0) ? g_qb : (part == 1) ? g_k1b
                                   : (part == 2) ? g_k2b : g_vb;
                if (part < 3) {
                    float v[16];
                    #pragma unroll
                    for (int j = 0; j < 8; j++) {
                        __nv_bfloat162 p = *(__nv_bfloat162*)&wd[j];
                        float a = __bfloat162float(p.x), bq = __bfloat162float(p.y);
                        v[2*j]   = (a  > 0.f) ? (a  + 1.f) : __expf(a);
                        v[2*j+1] = (bq > 0.f) ? (bq + 1.f) : __expf(bq);
                    }
                    float s = 0.f;
                    #pragma unroll
                    for (int j = 0; j < 16; j++) s += v[j];
                    s += __shfl_xor_sync(0xFFFFFFFFu, s, 1);
                    s += __shfl_xor_sync(0xFFFFFFFFu, s, 2);
                    float inv = 1.f / s;
                    #pragma unroll
                    for (int j = 0; j < 8; j++)
                        wd[j] = packbf(v[2*j] * inv, v[2*j+1] * inv);
                }
                int l = m >> 6, b = m & 63;
                __nv_bfloat16* rowp = dst + (((size_t)(b * H_ + head) * L_ + l) << 6) + 16 * ql;
                *(uint4*)rowp       = make_uint4(wd[0], wd[1], wd[2], wd[3]);
                *(uint4*)(rowp + 8) = make_uint4(wd[4], wd[5], wd[6], wd[7]);
            } else {
                __nv_bfloat16* rowp = outp + (size_t)m * N + n0 + wn * 64 + 16 * ql;
                *(uint4*)rowp       = make_uint4(wd[0], wd[1], wd[2], wd[3]);
                *(uint4*)(rowp + 8) = make_uint4(wd[4], wd[5], wd[6], wd[7]);
            }
        }
    }
}

// ---------------- fast-weight: register-resident S + merged O/W phase, last-chunk W skip ----------------
#define FW_SMEM (12 * 4096 * 2)   // 96KB

__device__ __forceinline__ int offe(int t, int r, int c) {
    return t * 4096 + r * 64 + ((((c >> 3) ^ (r & 7))) << 3) + (c & 7);
}

__global__ void __launch_bounds__(256) fw_kernel(const float* __restrict__ pi0,
                                                 __nv_bfloat16* __restrict__ lo)
{
    extern __shared__ __nv_bfloat16 fs[];
    const uint32_t sb = (uint32_t)__cvta_generic_to_shared(fs);
    const int bh = blockIdx.x, b = bh >> 4, h = bh & 15;
    const int tid = threadIdx.x, lane = tid & 31, warp = tid >> 5;
    const int g = warp >> 2, wg = warp & 3;
    const size_t base = (size_t)bh * (L_ * D_);
    const __nv_bfloat16* srcs[4] = { g_qb + base, g_k1b + base, g_k2b + base, g_vb + base };

    const int lr = tid >> 3, lcc = tid & 7;

    const int arow = 16 * wg + ((lane >> 3) & 1) * 8 + (lane & 7);
    const int ac0  = (lane >> 4);
    const int brow = (lane >> 4) * 8 + (lane & 7);
    const int bck  = ((lane >> 3) & 1);
    const int trow = ((lane >> 3) & 1) * 8 + (lane & 7);
    const int tck  = (lane >> 4);
    const int karow = (lane >> 4) * 8 + (lane & 7);
    const int kack  = ((lane >> 3) & 1);
    const int tlo = 16 * wg + (lane >> 2);
    const int cc0 = (lane & 3) * 2;

    float Wa[8][4], O[8][4];
    #pragma unroll
    for (int n = 0; n < 8; n++)
        #pragma unroll
        for (int q = 0; q < 4; q++) Wa[n][q] = 0.f;

    #pragma unroll
    for (int t = 0; t < 4; t++) {
        const __nv_bfloat16* sp = srcs[t];
        #pragma unroll
        for (int g2 = 0; g2 < 2; g2++) {
            int r = lr + 32 * g2;
            CP_ASYNC16(sb + 2u * offe(t, r, lcc * 8), sp + r * 64 + lcc * 8);
        }
    }
    CP_COMMIT();

    for (int c = 0; c < 4; c++) {
        __syncthreads();
        if (c + 1 < 4) {
            int s4 = ((c + 1) & 1) * 4;
            #pragma unroll
            for (int t = 0; t < 4; t++) {
                const __nv_bfloat16* sp = srcs[t] + (c + 1) * 4096;
                #pragma unroll
                for (int g2 = 0; g2 < 2; g2++) {
                    int r = lr + 32 * g2;
                    CP_ASYNC16(sb + 2u * offe(s4 + t, r, lcc * 8), sp + r * 64 + lcc * 8);
                }
            }
        }
        CP_COMMIT();
        CP_WAIT(1);

        if (c) {
            #pragma unroll
            for (int n = 0; n < 8; n++) {
                #pragma unroll
                for (int hf = 0; hf < 2; hf++) {
                    int r = 16 * wg + (lane >> 2) + 8 * hf;
                    *(__nv_bfloat162*)&fs[offe(10 + g, r, 8 * n + cc0)] =
                        __floats2bfloat162_rn(Wa[n][2*hf], Wa[n][2*hf+1]);
                }
            }
        }
        __syncthreads();

        const int tb = (c & 1) * 4;

        uint32_t QA[4][4];
        #pragma unroll
        for (int ks = 0; ks < 4; ks++)
            ldsm4(sb + 2u * offe(tb + 0, arow, (2 * ks + ac0) * 8), QA[ks][0], QA[ks][1], QA[ks][2], QA[ks][3]);

        #pragma unroll
        for (int n = 0; n < 8; n++)
            #pragma unroll
            for (int q = 0; q < 4; q++) O[n][q] = 0.f;
        #pragma unroll
        for (int ks = 0; ks < 4; ks++)
            #pragma unroll
            for (int np = 0; np < 4; np++) {
                uint32_t b0, b1, b2, b3;
                ldsm4(sb + 2u * offe(tb + 1 + g, 16 * np + brow, (2 * ks + bck) * 8), b0, b1, b2, b3);
                mma_bf16(O[2*np][0], O[2*np][1], O[2*np][2], O[2*np][3],
                         QA[ks][0], QA[ks][1], QA[ks][2], QA[ks][3], b0, b1);
                mma_bf16(O[2*np+1][0], O[2*np+1][1], O[2*np+1][2], O[2*np+1][3],
                         QA[ks][0], QA[ks][1], QA[ks][2], QA[ks][3], b2, b3);
            }

        uint32_t SA[4][4];
        #pragma unroll
        for (int kb = 0; kb < 4; kb++) {
            #pragma unroll
            for (int half = 0; half < 2; half++) {
                int nt = 2 * kb + half;
                int s0 = 8 * nt + cc0;
                float v0 = (s0     <= tlo) ? O[nt][0] : 0.f;
                float v1 = (s0 + 1 <= tlo) ? O[nt][1] : 0.f;
                float v2 = (s0     <= tlo + 8) ? O[nt][2] : 0.f;
                float v3 = (s0 + 1 <= tlo + 8) ? O[nt][3] : 0.f;
                SA[kb][2*half]     = packbf(v0, v1);
                SA[kb][2*half + 1] = packbf(v2, v3);
            }
        }
        #pragma unroll
        for (int n = 0; n < 8; n++)
            #pragma unroll
            for (int q = 0; q < 4; q++) O[n][q] = 0.f;

        #pragma unroll
        for (int ks = 0; ks < 4; ks++) {
            uint32_t KA[4];
            if (c < 3)
                ldsm4t(sb + 2u * offe(tb + 1 + g, 16 * ks + karow, (2 * wg + kack) * 8),
                       KA[0], KA[1], KA[2], KA[3]);
            #pragma unroll
            for (int np = 0; np < 4; np++) {
                uint32_t vb0, vb1, vb2, vb3;
                ldsm4t(sb + 2u * offe(tb + 3, 16 * ks + trow, (2 * np + tck) * 8), vb0, vb1, vb2, vb3);
                mma_bf16(O[2*np][0], O[2*np][1], O[2*np][2], O[2*np][3],
                         SA[ks][0], SA[ks][1], SA[ks][2], SA[ks][3], vb0, vb1);
                mma_bf16(O[2*np+1][0], O[2*np+1][1], O[2*np+1][2], O[2*np+1][3],
                         SA[ks][0], SA[ks][1], SA[ks][2], SA[ks][3], vb2, vb3);
                if (c < 3) {
                    mma_bf16(Wa[2*np][0], Wa[2*np][1], Wa[2*np][2], Wa[2*np][3],
                             KA[0], KA[1], KA[2], KA[3], vb0, vb1);
                    mma_bf16(Wa[2*np+1][0], Wa[2*np+1][1], Wa[2*np+1][2], Wa[2*np+1][3],
                             KA[0], KA[1], KA[2], KA[3], vb2, vb3);
                }
                if (c) {
                    uint32_t wb0, wb1, wb2, wb3;
                    ldsm4t(sb + 2u * offe(10 + g, 16 * ks + trow, (2 * np + tck) * 8), wb0, wb1, wb2, wb3);
                    mma_bf16(O[2*np][0], O[2*np][1], O[2*np][2], O[2*np][3],
                             QA[ks][0], QA[ks][1], QA[ks][2], QA[ks][3], wb0, wb1);
                    mma_bf16(O[2*np+1][0], O[2*np+1][1], O[2*np+1][2], O[2*np+1][3],
                             QA[ks][0], QA[ks][1], QA[ks][2], QA[ks][3], wb2, wb3);
                }
            }
        }

        {
            int l0 = c * 64 + tlo, l1 = l0 + 8;
            float p0 = fminf(fmaxf(pi0[h * 256 + l0], 0.f), 1.f);
            float p1 = fminf(fmaxf(pi0[h * 256 + l1], 0.f), 1.f);
            if (g == 1) {
                float q0 = SCALE_ * (1.f - p0), q1 = SCALE_ * (1.f - p1);
                #pragma unroll
                for (int nt = 0; nt < 8; nt++) {
                    int s0 = 8 * nt + cc0;
                    *(__nv_bfloat162*)&fs[offe(9, tlo, s0)]     = __floats2bfloat162_rn(q0 * O[nt][0], q0 * O[nt][1]);
                    *(__nv_bfloat162*)&fs[offe(9, tlo + 8, s0)] = __floats2bfloat162_rn(q1 * O[nt][2], q1 * O[nt][3]);
                }
            }
            __syncthreads();
            if (g == 0) {
                float q0 = SCALE_ * p0, q1 = SCALE_ * p1;
                size_t ro0 = ((size_t)(l0 * B_ + b)) * HD_ + h * 64;
                size_t ro1 = ((size_t)(l1 * B_ + b)) * HD_ + h * 64;
                #pragma unroll
                for (int nt = 0; nt < 8; nt++) {
                    int e0 = 8 * nt + cc0;
                    __nv_bfloat162 x0 = *(__nv_bfloat162*)&fs[offe(9, tlo, e0)];
                    __nv_bfloat162 x1 = *(__nv_bfloat162*)&fs[offe(9, tlo + 8, e0)];
                    float f0 = q0 * O[nt][0] + __bfloat162float(x0.x);
                    float f1 = q0 * O[nt][1] + __bfloat162float(x0.y);
                    float f2 = q1 * O[nt][2] + __bfloat162float(x1.x);
                    float f3 = q1 * O[nt][3] + __bfloat162float(x1.y);
                    *(__nv_bfloat162*)&lo[ro0 + e0] = __floats2bfloat162_rn(f0, f1);
                    *(__nv_bfloat162*)&lo[ro1 + e0] = __floats2bfloat162_rn(f2, f3);
                }
            }
        }
    }
}

// ---------------- residual + LayerNorm: warp-per-row ----------------
__global__ void __launch_bounds__(256) ln_kernel(const float* __restrict__ hin,
                                                 const __nv_bfloat16* __restrict__ attn,
                                                 const float* __restrict__ gamma,
                                                 const float* __restrict__ beta,
                                                 float* __restrict__ out)
{
    const int warp = threadIdx.x >> 5, lane = threadIdx.x & 31;
    const int row = blockIdx.x * 8 + warp;
    const float4* hr = (const float4*)(hin + (size_t)row * DM_);
    const uint2*  ar = (const uint2*)(attn + (size_t)row * DM_);

    float x[32];
    float s = 0.f, sq = 0.f;
    #pragma unroll
    for (int j = 0; j < 8; j++) {
        float4 hv = hr[lane + 32 * j];
        uint2 ap = ar[lane + 32 * j];
        __nv_bfloat162 a0 = *(__nv_bfloat162*)&ap.x;
        __nv_bfloat162 a1 = *(__nv_bfloat162*)&ap.y;
        float v0 = hv.x + __bfloat162float(a0.x);
        float v1 = hv.y + __bfloat162float(a0.y);
        float v2 = hv.z + __bfloat162float(a1.x);
        float v3 = hv.w + __bfloat162float(a1.y);
        x[4*j] = v0; x[4*j+1] = v1; x[4*j+2] = v2; x[4*j+3] = v3;
        s  += v0 + v1 + v2 + v3;
        sq += v0*v0 + v1*v1 + v2*v2 + v3*v3;
    }
    #pragma unroll
    for (int o = 16; o > 0; o >>= 1) {
        s  += __shfl_xor_sync(0xFFFFFFFFu, s,  o);
        sq += __shfl_xor_sync(0xFFFFFFFFu, sq, o);
    }
    float mu  = s * (1.f / DM_);
    float var = sq * (1.f / DM_) - mu * mu;
    float inv = rsqrtf(var + LN_EPS_);

    float4* orow = (float4*)(out + (size_t)row * DM_);
    #pragma unroll
    for (int j = 0; j < 8; j++) {
        float4 g4 = ((const float4*)gamma)[lane + 32 * j];
        float4 b4 = ((const float4*)beta)[lane + 32 * j];
        float4 o4;
        o4.x = (x[4*j]   - mu) * inv * g4.x + b4.x;
        o4.y = (x[4*j+1] - mu) * inv * g4.y + b4.y;
        o4.z = (x[4*j+2] - mu) * inv * g4.z + b4.z;
        o4.w = (x[4*j+3] - mu) * inv * g4.w + b4.w;
        orow[lane + 32 * j] = o4;
    }
}

// ---------------- launch ----------------
extern "C" void kernel_launch(void* const* d_in, const int* in_sizes, int n_in,
                              void* d_out, int out_size) {
    (void)in_sizes; (void)n_in; (void)out_size;
    const float* h      = (const float*)d_in[0];
    const float* qkv_w  = (const float*)d_in[1];
    const float* o_w    = (const float*)d_in[2];
    const float* gamma  = (const float*)d_in[3];
    const float* beta   = (const float*)d_in[4];
    const float* pi0    = (const float*)d_in[5];
    float* out = (float*)d_out;

    __nv_bfloat16 *hb, *wqkv, *wo, *lo, *attnb;
    cudaGetSymbolAddress((void**)&hb,    g_hb);
    cudaGetSymbolAddress((void**)&wqkv,  g_wqkv);
    cudaGetSymbolAddress((void**)&wo,    g_wo);
    cudaGetSymbolAddress((void**)&lo,    g_lo);
    cudaGetSymbolAddress((void**)&attnb, g_attnb);

    cudaFuncSetAttribute(gemm_nt<0>, cudaFuncAttributeMaxDynamicSharedMemorySize, GEMM_SMEM);
    cudaFuncSetAttribute(gemm_nt<1>, cudaFuncAttributeMaxDynamicSharedMemorySize, GEMM_SMEM);
    cudaFuncSetAttribute(fw_kernel,  cudaFuncAttributeMaxDynamicSharedMemorySize, FW_SMEM);

    cast_all<<<(H4_ + Q4_ + O4_ + 255) / 256, 256>>>(h, qkv_w, o_w);

    gemm_nt<0><<<dim3(N1_/128, M_/128), 256, GEMM_SMEM>>>(hb, wqkv, M_, N1_, DM_, nullptr);

    fw_kernel<<<B_*H_, 256, FW_SMEM>>>(pi0, lo);

    gemm_nt<1><<<dim3(HD_/128, M_/128), 256, GEMM_SMEM>>>(lo, wo, M_, HD_, HD_, attnb);

    ln_kernel<<<M_/8, 256>>>(h, attnb, gamma, beta, out);
}

// round 17
// speedup vs baseline: 1.1510x; 1.0159x over previous
#include <cuda_runtime.h>
#include <cuda_bf16.h>
#include <cstdint>

#define H_  16
#define D_  64
#define DM_ 1024
#define L_  256
#define B_  64
#define M_  (L_*B_)       // 16384
#define N1_ (H_*4*D_)     // 4096
#define HD_ (H_*D_)       // 1024
#define SCALE_ 0.125f
#define LN_EPS_ 1e-5f

// ---------------- scratch ----------------
__device__ __nv_bfloat16 g_hb[M_*DM_];
__device__ __nv_bfloat16 g_wqkv[N1_*DM_];
__device__ __nv_bfloat16 g_wo[DM_*HD_];
__device__ __nv_bfloat16 g_qb [B_*H_*L_*D_];  // post-phi bf16 [B,H,L,D]
__device__ __nv_bfloat16 g_k1b[B_*H_*L_*D_];
__device__ __nv_bfloat16 g_k2b[B_*H_*L_*D_];
__device__ __nv_bfloat16 g_vb [B_*H_*L_*D_];
__device__ __nv_bfloat16 g_lo[M_*HD_];        // gated layer_out
__device__ __nv_bfloat16 g_attnb[M_*DM_];     // attn_out bf16

// ---------------- merged cast kernel ----------------
#define H4_ (M_*DM_/4)
#define Q4_ (N1_*DM_/4)
#define O4_ (DM_*HD_/4)

__global__ void __launch_bounds__(256) cast_all(const float* __restrict__ h,
                                                const float* __restrict__ wq,
                                                const float* __restrict__ wo)
{
    int i = blockIdx.x * blockDim.x + threadIdx.x;
    const float* src;
    __nv_bfloat16* dst;
    int j;
    if (i < H4_)            { src = h;  dst = g_hb;   j = i; }
    else if (i < H4_ + Q4_) { src = wq; dst = g_wqkv; j = i - H4_; }
    else if (i < H4_ + Q4_ + O4_) { src = wo; dst = g_wo; j = i - H4_ - Q4_; }
    else return;
    float4 f = ((const float4*)src)[j];
    __nv_bfloat162* o = ((__nv_bfloat162*)dst) + j * 2;
    o[0] = __floats2bfloat162_rn(f.x, f.y);
    o[1] = __floats2bfloat162_rn(f.z, f.w);
}

// ---------------- mma/ldsm helpers ----------------
__device__ __forceinline__ void mma_bf16(float& d0, float& d1, float& d2, float& d3,
                                         uint32_t a0, uint32_t a1, uint32_t a2, uint32_t a3,
                                         uint32_t b0, uint32_t b1) {
    asm volatile(
        "mma.sync.aligned.m16n8k16.row.col.f32.bf16.bf16.f32 "
        "{%0,%1,%2,%3},{%4,%5,%6,%7},{%8,%9},{%0,%1,%2,%3};\n"
        : "+f"(d0), "+f"(d1), "+f"(d2), "+f"(d3)
        : "r"(a0), "r"(a1), "r"(a2), "r"(a3), "r"(b0), "r"(b1));
}
__device__ __forceinline__ void ldsm4(uint32_t a, uint32_t& r0, uint32_t& r1, uint32_t& r2, uint32_t& r3) {
    asm volatile("ldmatrix.sync.aligned.m8n8.x4.shared.b16 {%0,%1,%2,%3},[%4];"
                 : "=r"(r0), "=r"(r1), "=r"(r2), "=r"(r3) : "r"(a));
}
__device__ __forceinline__ void ldsm4t(uint32_t a, uint32_t& r0, uint32_t& r1, uint32_t& r2, uint32_t& r3) {
    asm volatile("ldmatrix.sync.aligned.m8n8.x4.trans.shared.b16 {%0,%1,%2,%3},[%4];"
                 : "=r"(r0), "=r"(r1), "=r"(r2), "=r"(r3) : "r"(a));
}
__device__ __forceinline__ uint32_t packbf(float a, float b) {
    __nv_bfloat162 t = __floats2bfloat162_rn(a, b);
    return *(uint32_t*)&t;
}
#define CP_ASYNC16(dst, src) asm volatile("cp.async.cg.shared.global [%0], [%1], 16;" :: "r"(dst), "l"(src))
#define CP_COMMIT() asm volatile("cp.async.commit_group;")
#define CP_WAIT(n)  asm volatile("cp.async.wait_group %0;" :: "n"(n))

// ---------------- quad transpose (gemm epilogues) ----------------
__device__ __forceinline__ void quad_transpose(const uint32_t pk[8], uint32_t wout[8], int lane) {
    const int ql = lane & 3;
    const bool hi2 = (ql & 2) != 0;
    const bool hi1 = (ql & 1) != 0;
    uint32_t kA0 = hi2 ? pk[4] : pk[0];
    uint32_t kA1 = hi2 ? pk[5] : pk[1];
    uint32_t kA2 = hi2 ? pk[6] : pk[2];
    uint32_t kA3 = hi2 ? pk[7] : pk[3];
    uint32_t sA0 = hi2 ? pk[0] : pk[4];
    uint32_t sA1 = hi2 ? pk[1] : pk[5];
    uint32_t sA2 = hi2 ? pk[2] : pk[6];
    uint32_t sA3 = hi2 ? pk[3] : pk[7];
    uint32_t rA0 = __shfl_xor_sync(0xFFFFFFFFu, sA0, 2);
    uint32_t rA1 = __shfl_xor_sync(0xFFFFFFFFu, sA1, 2);
    uint32_t rA2 = __shfl_xor_sync(0xFFFFFFFFu, sA2, 2);
    uint32_t rA3 = __shfl_xor_sync(0xFFFFFFFFu, sA3, 2);
    uint32_t k0 = hi1 ? kA2 : kA0;
    uint32_t k1 = hi1 ? kA3 : kA1;
    uint32_t r0 = hi1 ? rA2 : rA0;
    uint32_t r1 = hi1 ? rA3 : rA1;
    uint32_t sB0 = hi1 ? kA0 : kA2;
    uint32_t sB1 = hi1 ? kA1 : kA3;
    uint32_t sB2 = hi1 ? rA0 : rA2;
    uint32_t sB3 = hi1 ? rA1 : rA3;
    uint32_t b0 = __shfl_xor_sync(0xFFFFFFFFu, sB0, 1);
    uint32_t b1 = __shfl_xor_sync(0xFFFFFFFFu, sB1, 1);
    uint32_t b2 = __shfl_xor_sync(0xFFFFFFFFu, sB2, 1);
    uint32_t b3 = __shfl_xor_sync(0xFFFFFFFFu, sB3, 1);
    #pragma unroll
    for (int h = 0; h < 2; h++) {
        uint32_t a = h ? k1 : k0;
        uint32_t bb = h ? b1 : b0;
        uint32_t cc = h ? r1 : r0;
        uint32_t dd = h ? b3 : b2;
        if (hi1) { uint32_t t = a; a = bb; bb = t; t = cc; cc = dd; dd = t; }
        if (hi2) { uint32_t t = a; a = cc; cc = t; t = bb; bb = dd; dd = t; }
        wout[h * 4 + 0] = a; wout[h * 4 + 1] = bb;
        wout[h * 4 + 2] = cc; wout[h * 4 + 3] = dd;
    }
}

// ---------------- bf16 NT GEMM, 128x128x64, 3-stage cp.async, K-phase desync ----------------
// mofs/nofs allow head-group / M-half partial launches for stream overlap.
#define GEMM_SMEM (3 * 32768)   // 96KB

template<int EPI>
__global__ void __launch_bounds__(256, 2) gemm_nt(
    const __nv_bfloat16* __restrict__ A, const __nv_bfloat16* __restrict__ Bw,
    int M, int N, int K, __nv_bfloat16* __restrict__ outp, int mofs, int nofs)
{
    extern __shared__ __nv_bfloat16 gsm[];
    const uint32_t smb = (uint32_t)__cvta_generic_to_shared(gsm);

    const int tid = threadIdx.x, lane = tid & 31, w = tid >> 5;
    const int wm = w & 3, wn = w >> 2;
    const int m0 = blockIdx.y * 128 + mofs, n0 = blockIdx.x * 128 + nofs;

    const int lr = tid >> 3, lcc = tid & 7;
    const __nv_bfloat16* Ag = A + (size_t)(m0 + lr) * K + lcc * 8;
    const __nv_bfloat16* Bg = Bw + (size_t)(n0 + lr) * K + lcc * 8;
    uint32_t stoff[4];
    #pragma unroll
    for (int g = 0; g < 4; g++) {
        int r = lr + 32 * g;
        stoff[g] = r * 128 + ((lcc ^ (r & 7)) * 16);
    }

    const int aRow = wm * 32 + ((lane >> 3) & 1) * 8 + (lane & 7);
    const int aCk  = (lane >> 4);
    const int bRow = wn * 64 + (lane >> 4) * 8 + (lane & 7);
    const int bCk  = ((lane >> 3) & 1);

    float acc[2][8][4];
    #pragma unroll
    for (int i = 0; i < 2; i++)
        #pragma unroll
        for (int j = 0; j < 8; j++)
            #pragma unroll
            for (int k = 0; k < 4; k++) acc[i][j][k] = 0.f;

    const int nk = K >> 6;
    const int kbase = ((blockIdx.x + blockIdx.y) & 1) * (nk >> 1);

    #pragma unroll
    for (int s = 0; s < 2; s++) {
        int kb = (s + kbase) & (nk - 1);
        uint32_t ab = smb + s * 32768u, bb = ab + 16384u;
        #pragma unroll
        for (int g = 0; g < 4; g++) {
            CP_ASYNC16(ab + stoff[g], Ag + (size_t)(32 * g) * K + kb * 64);
            CP_ASYNC16(bb + stoff[g], Bg + (size_t)(32 * g) * K + kb * 64);
        }
        CP_COMMIT();
    }

    for (int i = 0; i < nk; i++) {
        CP_WAIT(1);
        __syncthreads();
        if (i + 2 < nk) {
            int st = (i + 2) % 3;
            int kbn = (i + 2 + kbase) & (nk - 1);
            uint32_t ab = smb + st * 32768u, bb = ab + 16384u;
            #pragma unroll
            for (int g = 0; g < 4; g++) {
                CP_ASYNC16(ab + stoff[g], Ag + (size_t)(32 * g) * K + kbn * 64);
                CP_ASYNC16(bb + stoff[g], Bg + (size_t)(32 * g) * K + kbn * 64);
            }
        }
        CP_COMMIT();

        const uint32_t ab = smb + (i % 3) * 32768u;
        const uint32_t bb = ab + 16384u;
        #pragma unroll
        for (int kk8 = 0; kk8 < 8; kk8 += 2) {
            uint32_t af[2][4], bfr[4][4];
            #pragma unroll
            for (int mt = 0; mt < 2; mt++) {
                int r = aRow + mt * 16, ck = kk8 + aCk;
                ldsm4(ab + r * 128 + ((ck ^ (r & 7)) * 16), af[mt][0], af[mt][1], af[mt][2], af[mt][3]);
            }
            #pragma unroll
            for (int np = 0; np < 4; np++) {
                int r = bRow + np * 16, ck = kk8 + bCk;
                ldsm4(bb + r * 128 + ((ck ^ (r & 7)) * 16), bfr[np][0], bfr[np][1], bfr[np][2], bfr[np][3]);
            }
            #pragma unroll
            for (int mt = 0; mt < 2; mt++)
                #pragma unroll
                for (int np = 0; np < 4; np++) {
                    mma_bf16(acc[mt][2*np][0], acc[mt][2*np][1], acc[mt][2*np][2], acc[mt][2*np][3],
                             af[mt][0], af[mt][1], af[mt][2], af[mt][3], bfr[np][0], bfr[np][1]);
                    mma_bf16(acc[mt][2*np+1][0], acc[mt][2*np+1][1], acc[mt][2*np+1][2], acc[mt][2*np+1][3],
                             af[mt][0], af[mt][1], af[mt][2], af[mt][3], bfr[np][2], bfr[np][3]);
                }
        }
    }

    // ---------------- epilogue (quad-transposed 16B stores) ----------------
    const int ql = lane & 3;
    #pragma unroll
    for (int mt = 0; mt < 2; mt++) {
        #pragma unroll
        for (int rr = 0; rr < 2; rr++) {
            int m = m0 + wm * 32 + mt * 16 + (lane >> 2) + rr * 8;
            uint32_t pk[8], wd[8];
            #pragma unroll
            for (int nt = 0; nt < 8; nt++)
                pk[nt] = packbf(acc[mt][nt][rr * 2], acc[mt][nt][rr * 2 + 1]);
            quad_transpose(pk, wd, lane);

            if (EPI == 0) {
                const int c0base = n0 + wn * 64;
                const int head = c0base >> 8, part = (c0base >> 6) & 3;
                __nv_bfloat16* dst = (part == 0) ? g_qb : (part == 1) ? g_k1b
                                   : (part == 2) ? g_k2b : g_vb;
                if (part < 3) {
                    float v[16];
                    #pragma unroll
                    for (int j = 0; j < 8; j++) {
                        __nv_bfloat162 p = *(__nv_bfloat162*)&wd[j];
                        float a = __bfloat162float(p.x), bq = __bfloat162float(p.y);
                        v[2*j]   = (a  > 0.f) ? (a  + 1.f) : __expf(a);
                        v[2*j+1] = (bq > 0.f) ? (bq + 1.f) : __expf(bq);
                    }
                    float s = 0.f;
                    #pragma unroll
                    for (int j = 0; j < 16; j++) s += v[j];
                    s += __shfl_xor_sync(0xFFFFFFFFu, s, 1);
                    s += __shfl_xor_sync(0xFFFFFFFFu, s, 2);
                    float inv = 1.f / s;
                    #pragma unroll
                    for (int j = 0; j < 8; j++)
                        wd[j] = packbf(v[2*j] * inv, v[2*j+1] * inv);
                }
                int l = m >> 6, b = m & 63;
                __nv_bfloat16* rowp = dst + (((size_t)(b * H_ + head) * L_ + l) << 6) + 16 * ql;
                *(uint4*)rowp       = make_uint4(wd[0], wd[1], wd[2], wd[3]);
                *(uint4*)(rowp + 8) = make_uint4(wd[4], wd[5], wd[6], wd[7]);
            } else {
                __nv_bfloat16* rowp = outp + (size_t)m * N + n0 + wn * 64 + 16 * ql;
                *(uint4*)rowp       = make_uint4(wd[0], wd[1], wd[2], wd[3]);
                *(uint4*)(rowp + 8) = make_uint4(wd[4], wd[5], wd[6], wd[7]);
            }
        }
    }
}

// ---------------- fast-weight (head-group launchable) ----------------
#define FW_SMEM (12 * 4096 * 2)   // 96KB

__device__ __forceinline__ int offe(int t, int r, int c) {
    return t * 4096 + r * 64 + ((((c >> 3) ^ (r & 7))) << 3) + (c & 7);
}

__global__ void __launch_bounds__(256) fw_kernel(const float* __restrict__ pi0,
                                                 __nv_bfloat16* __restrict__ lo,
                                                 int hbase)
{
    extern __shared__ __nv_bfloat16 fs[];
    const uint32_t sb = (uint32_t)__cvta_generic_to_shared(fs);
    const int b = blockIdx.x >> 2, h = hbase + (blockIdx.x & 3);
    const int bh = b * 16 + h;
    const int tid = threadIdx.x, lane = tid & 31, warp = tid >> 5;
    const int g = warp >> 2, wg = warp & 3;
    const size_t base = (size_t)bh * (L_ * D_);
    const __nv_bfloat16* srcs[4] = { g_qb + base, g_k1b + base, g_k2b + base, g_vb + base };

    const int lr = tid >> 3, lcc = tid & 7;

    const int arow = 16 * wg + ((lane >> 3) & 1) * 8 + (lane & 7);
    const int ac0  = (lane >> 4);
    const int brow = (lane >> 4) * 8 + (lane & 7);
    const int bck  = ((lane >> 3) & 1);
    const int trow = ((lane >> 3) & 1) * 8 + (lane & 7);
    const int tck  = (lane >> 4);
    const int karow = (lane >> 4) * 8 + (lane & 7);
    const int kack  = ((lane >> 3) & 1);
    const int tlo = 16 * wg + (lane >> 2);
    const int cc0 = (lane & 3) * 2;

    float Wa[8][4], O[8][4];
    #pragma unroll
    for (int n = 0; n < 8; n++)
        #pragma unroll
        for (int q = 0; q < 4; q++) Wa[n][q] = 0.f;

    #pragma unroll
    for (int t = 0; t < 4; t++) {
        const __nv_bfloat16* sp = srcs[t];
        #pragma unroll
        for (int g2 = 0; g2 < 2; g2++) {
            int r = lr + 32 * g2;
            CP_ASYNC16(sb + 2u * offe(t, r, lcc * 8), sp + r * 64 + lcc * 8);
        }
    }
    CP_COMMIT();

    for (int c = 0; c < 4; c++) {
        __syncthreads();
        if (c + 1 < 4) {
            int s4 = ((c + 1) & 1) * 4;
            #pragma unroll
            for (int t = 0; t < 4; t++) {
                const __nv_bfloat16* sp = srcs[t] + (c + 1) * 4096;
                #pragma unroll
                for (int g2 = 0; g2 < 2; g2++) {
                    int r = lr + 32 * g2;
                    CP_ASYNC16(sb + 2u * offe(s4 + t, r, lcc * 8), sp + r * 64 + lcc * 8);
                }
            }
        }
        CP_COMMIT();
        CP_WAIT(1);

        if (c) {
            #pragma unroll
            for (int n = 0; n < 8; n++) {
                #pragma unroll
                for (int hf = 0; hf < 2; hf++) {
                    int r = 16 * wg + (lane >> 2) + 8 * hf;
                    *(__nv_bfloat162*)&fs[offe(10 + g, r, 8 * n + cc0)] =
                        __floats2bfloat162_rn(Wa[n][2*hf], Wa[n][2*hf+1]);
                }
            }
        }
        __syncthreads();

        const int tb = (c & 1) * 4;

        uint32_t QA[4][4];
        #pragma unroll
        for (int ks = 0; ks < 4; ks++)
            ldsm4(sb + 2u * offe(tb + 0, arow, (2 * ks + ac0) * 8), QA[ks][0], QA[ks][1], QA[ks][2], QA[ks][3]);

        #pragma unroll
        for (int n = 0; n < 8; n++)
            #pragma unroll
            for (int q = 0; q < 4; q++) O[n][q] = 0.f;
        #pragma unroll
        for (int ks = 0; ks < 4; ks++)
            #pragma unroll
            for (int np = 0; np < 4; np++) {
                uint32_t b0, b1, b2, b3;
                ldsm4(sb + 2u * offe(tb + 1 + g, 16 * np + brow, (2 * ks + bck) * 8), b0, b1, b2, b3);
                mma_bf16(O[2*np][0], O[2*np][1], O[2*np][2], O[2*np][3],
                         QA[ks][0], QA[ks][1], QA[ks][2], QA[ks][3], b0, b1);
                mma_bf16(O[2*np+1][0], O[2*np+1][1], O[2*np+1][2], O[2*np+1][3],
                         QA[ks][0], QA[ks][1], QA[ks][2], QA[ks][3], b2, b3);
            }

        uint32_t SA[4][4];
        #pragma unroll
        for (int kb = 0; kb < 4; kb++) {
            #pragma unroll
            for (int half = 0; half < 2; half++) {
                int nt = 2 * kb + half;
                int s0 = 8 * nt + cc0;
                float v0 = (s0     <= tlo) ? O[nt][0] : 0.f;
                float v1 = (s0 + 1 <= tlo) ? O[nt][1] : 0.f;
                float v2 = (s0     <= tlo + 8) ? O[nt][2] : 0.f;
                float v3 = (s0 + 1 <= tlo + 8) ? O[nt][3] : 0.f;
                SA[kb][2*half]     = packbf(v0, v1);
                SA[kb][2*half + 1] = packbf(v2, v3);
            }
        }
        #pragma unroll
        for (int n = 0; n < 8; n++)
            #pragma unroll
            for (int q = 0; q < 4; q++) O[n][q] = 0.f;

        #pragma unroll
        for (int ks = 0; ks < 4; ks++) {
            uint32_t KA[4];
            if (c < 3)
                ldsm4t(sb + 2u * offe(tb + 1 + g, 16 * ks + karow, (2 * wg + kack) * 8),
                       KA[0], KA[1], KA[2], KA[3]);
            #pragma unroll
            for (int np = 0; np < 4; np++) {
                uint32_t vb0, vb1, vb2, vb3;
                ldsm4t(sb + 2u * offe(tb + 3, 16 * ks + trow, (2 * np + tck) * 8), vb0, vb1, vb2, vb3);
                mma_bf16(O[2*np][0], O[2*np][1], O[2*np][2], O[2*np][3],
                         SA[ks][0], SA[ks][1], SA[ks][2], SA[ks][3], vb0, vb1);
                mma_bf16(O[2*np+1][0], O[2*np+1][1], O[2*np+1][2], O[2*np+1][3],
                         SA[ks][0], SA[ks][1], SA[ks][2], SA[ks][3], vb2, vb3);
                if (c < 3) {
                    mma_bf16(Wa[2*np][0], Wa[2*np][1], Wa[2*np][2], Wa[2*np][3],
                             KA[0], KA[1], KA[2], KA[3], vb0, vb1);
                    mma_bf16(Wa[2*np+1][0], Wa[2*np+1][1], Wa[2*np+1][2], Wa[2*np+1][3],
                             KA[0], KA[1], KA[2], KA[3], vb2, vb3);
                }
                if (c) {
                    uint32_t wb0, wb1, wb2, wb3;
                    ldsm4t(sb + 2u * offe(10 + g, 16 * ks + trow, (2 * np + tck) * 8), wb0, wb1, wb2, wb3);
                    mma_bf16(O[2*np][0], O[2*np][1], O[2*np][2], O[2*np][3],
                             QA[ks][0], QA[ks][1], QA[ks][2], QA[ks][3], wb0, wb1);
                    mma_bf16(O[2*np+1][0], O[2*np+1][1], O[2*np+1][2], O[2*np+1][3],
                             QA[ks][0], QA[ks][1], QA[ks][2], QA[ks][3], wb2, wb3);
                }
            }
        }

        {
            int l0 = c * 64 + tlo, l1 = l0 + 8;
            float p0 = fminf(fmaxf(pi0[h * 256 + l0], 0.f), 1.f);
            float p1 = fminf(fmaxf(pi0[h * 256 + l1], 0.f), 1.f);
            if (g == 1) {
                float q0 = SCALE_ * (1.f - p0), q1 = SCALE_ * (1.f - p1);
                #pragma unroll
                for (int nt = 0; nt < 8; nt++) {
                    int s0 = 8 * nt + cc0;
                    *(__nv_bfloat162*)&fs[offe(9, tlo, s0)]     = __floats2bfloat162_rn(q0 * O[nt][0], q0 * O[nt][1]);
                    *(__nv_bfloat162*)&fs[offe(9, tlo + 8, s0)] = __floats2bfloat162_rn(q1 * O[nt][2], q1 * O[nt][3]);
                }
            }
            __syncthreads();
            if (g == 0) {
                float q0 = SCALE_ * p0, q1 = SCALE_ * p1;
                size_t ro0 = ((size_t)(l0 * B_ + b)) * HD_ + h * 64;
                size_t ro1 = ((size_t)(l1 * B_ + b)) * HD_ + h * 64;
                #pragma unroll
                for (int nt = 0; nt < 8; nt++) {
                    int e0 = 8 * nt + cc0;
                    __nv_bfloat162 x0 = *(__nv_bfloat162*)&fs[offe(9, tlo, e0)];
                    __nv_bfloat162 x1 = *(__nv_bfloat162*)&fs[offe(9, tlo + 8, e0)];
                    float f0 = q0 * O[nt][0] + __bfloat162float(x0.x);
                    float f1 = q0 * O[nt][1] + __bfloat162float(x0.y);
                    float f2 = q1 * O[nt][2] + __bfloat162float(x1.x);
                    float f3 = q1 * O[nt][3] + __bfloat162float(x1.y);
                    *(__nv_bfloat162*)&lo[ro0 + e0] = __floats2bfloat162_rn(f0, f1);
                    *(__nv_bfloat162*)&lo[ro1 + e0] = __floats2bfloat162_rn(f2, f3);
                }
            }
        }
    }
}

// ---------------- residual + LayerNorm: warp-per-row (row-offset launchable) ----------------
__global__ void __launch_bounds__(256) ln_kernel(const float* __restrict__ hin,
                                                 const __nv_bfloat16* __restrict__ attn,
                                                 const float* __restrict__ gamma,
                                                 const float* __restrict__ beta,
                                                 float* __restrict__ out,
                                                 int rofs)
{
    const int warp = threadIdx.x >> 5, lane = threadIdx.x & 31;
    const int row = blockIdx.x * 8 + warp + rofs;
    const float4* hr = (const float4*)(hin + (size_t)row * DM_);
    const uint2*  ar = (const uint2*)(attn + (size_t)row * DM_);

    float x[32];
    float s = 0.f, sq = 0.f;
    #pragma unroll
    for (int j = 0; j < 8; j++) {
        float4 hv = hr[lane + 32 * j];
        uint2 ap = ar[lane + 32 * j];
        __nv_bfloat162 a0 = *(__nv_bfloat162*)&ap.x;
        __nv_bfloat162 a1 = *(__nv_bfloat162*)&ap.y;
        float v0 = hv.x + __bfloat162float(a0.x);
        float v1 = hv.y + __bfloat162float(a0.y);
        float v2 = hv.z + __bfloat162float(a1.x);
        float v3 = hv.w + __bfloat162float(a1.y);
        x[4*j] = v0; x[4*j+1] = v1; x[4*j+2] = v2; x[4*j+3] = v3;
        s  += v0 + v1 + v2 + v3;
        sq += v0*v0 + v1*v1 + v2*v2 + v3*v3;
    }
    #pragma unroll
    for (int o = 16; o > 0; o >>= 1) {
        s  += __shfl_xor_sync(0xFFFFFFFFu, s,  o);
        sq += __shfl_xor_sync(0xFFFFFFFFu, sq, o);
    }
    float mu  = s * (1.f / DM_);
    float var = sq * (1.f / DM_) - mu * mu;
    float inv = rsqrtf(var + LN_EPS_);

    float4* orow = (float4*)(out + (size_t)row * DM_);
    #pragma unroll
    for (int j = 0; j < 8; j++) {
        float4 g4 = ((const float4*)gamma)[lane + 32 * j];
        float4 b4 = ((const float4*)beta)[lane + 32 * j];
        float4 o4;
        o4.x = (x[4*j]   - mu) * inv * g4.x + b4.x;
        o4.y = (x[4*j+1] - mu) * inv * g4.y + b4.y;
        o4.z = (x[4*j+2] - mu) * inv * g4.z + b4.z;
        o4.w = (x[4*j+3] - mu) * inv * g4.w + b4.w;
        orow[lane + 32 * j] = o4;
    }
}

// ---------------- launch (two-stream head-group pipeline) ----------------
extern "C" void kernel_launch(void* const* d_in, const int* in_sizes, int n_in,
                              void* d_out, int out_size) {
    (void)in_sizes; (void)n_in; (void)out_size;
    const float* h      = (const float*)d_in[0];
    const float* qkv_w  = (const float*)d_in[1];
    const float* o_w    = (const float*)d_in[2];
    const float* gamma  = (const float*)d_in[3];
    const float* beta   = (const float*)d_in[4];
    const float* pi0    = (const float*)d_in[5];
    float* out = (float*)d_out;

    __nv_bfloat16 *hb, *wqkv, *wo, *lo, *attnb;
    cudaGetSymbolAddress((void**)&hb,    g_hb);
    cudaGetSymbolAddress((void**)&wqkv,  g_wqkv);
    cudaGetSymbolAddress((void**)&wo,    g_wo);
    cudaGetSymbolAddress((void**)&lo,    g_lo);
    cudaGetSymbolAddress((void**)&attnb, g_attnb);

    cudaFuncSetAttribute(gemm_nt<0>, cudaFuncAttributeMaxDynamicSharedMemorySize, GEMM_SMEM);
    cudaFuncSetAttribute(gemm_nt<1>, cudaFuncAttributeMaxDynamicSharedMemorySize, GEMM_SMEM);
    cudaFuncSetAttribute(fw_kernel,  cudaFuncAttributeMaxDynamicSharedMemorySize, FW_SMEM);

    // lazily created side stream + events (resource setup only; identical work every call)
    static cudaStream_t s1 = nullptr;
    static cudaEvent_t e_fork, e_d_done, e_s_done, e_join;
    if (s1 == nullptr) {
        cudaStreamCreateWithFlags(&s1, cudaStreamNonBlocking);
        cudaEventCreateWithFlags(&e_fork,   cudaEventDisableTiming);
        cudaEventCreateWithFlags(&e_d_done, cudaEventDisableTiming);
        cudaEventCreateWithFlags(&e_s_done, cudaEventDisableTiming);
        cudaEventCreateWithFlags(&e_join,   cudaEventDisableTiming);
    }
    cudaStream_t s0 = 0;   // default (capture-origin) stream

    // casts on s0, then fork
    cast_all<<<(H4_ + Q4_ + O4_ + 255) / 256, 256, 0, s0>>>(h, qkv_w, o_w);
    cudaEventRecord(e_fork, s0);
    cudaStreamWaitEvent(s1, e_fork, 0);

    // head-group pipeline: groups 0,2 on s0; groups 1,3 on s1.
    // gemm1 group g covers N columns [g*1024, g*1024+1024) = heads 4g..4g+3.
    for (int g = 0; g < 4; g += 2) {
        gemm_nt<0><<<dim3(8, 128), 256, GEMM_SMEM, s0>>>(hb, wqkv, M_, N1_, DM_, nullptr, 0, g * 1024);
        gemm_nt<0><<<dim3(8, 128), 256, GEMM_SMEM, s1>>>(hb, wqkv, M_, N1_, DM_, nullptr, 0, (g + 1) * 1024);
        fw_kernel<<<256, 256, FW_SMEM, s0>>>(pi0, lo, 4 * g);
        fw_kernel<<<256, 256, FW_SMEM, s1>>>(pi0, lo, 4 * (g + 1));
    }

    // cross-join: gemm2 needs all fw output
    cudaEventRecord(e_d_done, s0);
    cudaEventRecord(e_s_done, s1);
    cudaStreamWaitEvent(s0, e_s_done, 0);
    cudaStreamWaitEvent(s1, e_d_done, 0);

    // gemm2 + ln split into M-halves per stream
    gemm_nt<1><<<dim3(8, 64), 256, GEMM_SMEM, s0>>>(lo, wo, M_, HD_, HD_, attnb, 0, 0);
    gemm_nt<1><<<dim3(8, 64), 256, GEMM_SMEM, s1>>>(lo, wo, M_, HD_, HD_, attnb, 8192, 0);
    ln_kernel<<<1024, 256, 0, s0>>>(h, attnb, gamma, beta, out, 0);
    ln_kernel<<<1024, 256, 0, s1>>>(h, attnb, gamma, beta, out, 8192);

    // join back into capture-origin stream
    cudaEventRecord(e_join, s1);
    cudaStreamWaitEvent(s0, e_join, 0);
}